// round 6
// baseline (speedup 1.0000x reference)
#include <cuda_runtime.h>
#include <cstdint>

__device__ float g_y[8192*128], g_v[8192*128], g_v2[8192*128];

__device__ __forceinline__ void sp32(float x, uint32_t& h, uint32_t& l) {
    asm("cvt.rna.tf32.f32 %0, %1;" : "=r"(h) : "f"(x));
    float r = x - __uint_as_float(h);
    asm("cvt.rna.tf32.f32 %0, %1;" : "=r"(l) : "f"(r));
}
__device__ __forceinline__ void mma8(float* c, const uint32_t* a, uint32_t b0, uint32_t b1) {
    asm volatile(
        "mma.sync.aligned.m16n8k8.row.col.f32.tf32.tf32.f32 "
        "{%0,%1,%2,%3},{%4,%5,%6,%7},{%8,%9},{%0,%1,%2,%3};"
        : "+f"(c[0]), "+f"(c[1]), "+f"(c[2]), "+f"(c[3])
        : "r"(a[0]), "r"(a[1]), "r"(a[2]), "r"(a[3]), "r"(b0), "r"(b1));
}
__device__ __forceinline__ float sspf(float x) {
    return fmaxf(x, 0.f) + log1pf(__expf(-fabsf(x))) - 0.69314718055994531f;
}

// m16n8k8 tf32 x3 step. A smem row-major (lda), W smem row-major [N][ldb] (B=W^T).
template <int NBLK>
__device__ __forceinline__ void gstep(const float* As, int lda, int m0, int k0,
                                      const float* Ws, int ldb, int n0, int lane,
                                      float (*acc)[4]) {
    int g = lane >> 2, t = lane & 3;
    const float* p0 = As + (m0 + g) * lda + k0 + t;
    const float* p1 = p0 + 8 * lda;
    uint32_t ah[4], al[4];
    sp32(p0[0], ah[0], al[0]); sp32(p1[0], ah[1], al[1]);
    sp32(p0[4], ah[2], al[2]); sp32(p1[4], ah[3], al[3]);
#pragma unroll
    for (int j = 0; j < NBLK; ++j) {
        const float* w = Ws + (n0 + j * 8 + g) * ldb + k0 + t;
        uint32_t bh0, bl0, bh1, bl1;
        sp32(w[0], bh0, bl0); sp32(w[4], bh1, bl1);
        mma8(acc[j], ah, bh0, bh1);
        mma8(acc[j], ah, bl0, bl1);
        mma8(acc[j], al, bh0, bh1);
    }
}

// out[8192,128] = act(A[8192,128] @ W[128,128]^T + bias); doSsp: #ssp applications
__global__ __launch_bounds__(256, 1)
void gemm64_kernel(const float* __restrict__ A, const float* __restrict__ W,
                   const float* __restrict__ bias, float* __restrict__ out, int doSsp) {
    extern __shared__ __align__(16) float sm[];
    float* ws = sm;          // 128 x 132
    float* xs = sm + 16896;  // 64 x 132
    int tid = threadIdx.x, lane = tid & 31, warp = tid >> 5;
    int wm = warp & 3, wn = warp >> 2, g = lane >> 2, t = lane & 3;
    int row0 = blockIdx.x * 64;
    for (int i = tid; i < 4096; i += 256) {
        int r = i >> 5, c = i & 31;
        *(float4*)(ws + r * 132 + c * 4) = *(const float4*)(W + r * 128 + c * 4);
    }
    for (int i = tid; i < 2048; i += 256) {
        int r = i >> 5, c = i & 31;
        *(float4*)(xs + r * 132 + c * 4) = *(const float4*)(A + (size_t)(row0 + r) * 128 + c * 4);
    }
    __syncthreads();
    float acc[8][4]{};
#pragma unroll
    for (int ks = 0; ks < 16; ++ks)
        gstep<8>(xs, 132, wm * 16, ks * 8, ws, 132, wn * 64, lane, acc);
    int r0 = row0 + wm * 16 + g, r1 = r0 + 8;
#pragma unroll
    for (int j = 0; j < 8; ++j) {
        int n0 = wn * 64 + j * 8 + 2 * t;
        float b0 = bias ? bias[n0] : 0.f, b1 = bias ? bias[n0 + 1] : 0.f;
        float v00 = acc[j][0] + b0, v01 = acc[j][1] + b1;
        float v10 = acc[j][2] + b0, v11 = acc[j][3] + b1;
        for (int s = 0; s < doSsp; ++s) {
            v00 = sspf(v00); v01 = sspf(v01); v10 = sspf(v10); v11 = sspf(v11);
        }
        *(float2*)(out + (size_t)r0 * 128 + n0) = make_float2(v00, v01);
        *(float2*)(out + (size_t)r1 * 128 + n0) = make_float2(v10, v11);
    }
}

// fused: GEMM1(fij@Wf1^T,+b1,ssp) -> GEMM2(@Wf2^T,+b2) -> *cutoff*mask -> gather y -> sum_n
__global__ __launch_bounds__(256, 1)
void main_kernel(const float* __restrict__ fij, const float* __restrict__ rij,
                 const int* __restrict__ nbrs, const float* __restrict__ nmask,
                 const float* __restrict__ b1, const float* __restrict__ b2,
                 const float* __restrict__ Wf1, const float* __restrict__ Wf2,
                 const float* __restrict__ Y, float* __restrict__ V) {
    extern __shared__ __align__(16) float sm[];
    float* wf1 = sm;           // 128 x 60  (cols 50..59 zero)
    float* wf2 = sm + 7680;    // 128 x 132
    float* fjs = sm + 24576;   // 64 x 60   (cols 50..59 zero)
    float* w1s = sm + 28416;   // 64 x 132
    float* wts = sm + 36864;   // 64 x 132
    float* prs = sm + 45312;   // 256
    float* cms = sm + 45568;   // 64
    int*   nbs = (int*)(sm + 45632); // 64
    float* b1s = sm + 45696;   // 128
    float* b2s = sm + 45824;   // 128
    int tid = threadIdx.x, lane = tid & 31, warp = tid >> 5;
    int wm = warp & 3, wn = warp >> 2, g = lane >> 2, t = lane & 3;

    for (int i = tid; i < 6400; i += 256) { int r = i / 50, c = i - r * 50; wf1[r * 60 + c] = Wf1[i]; }
    for (int i = tid; i < 1280; i += 256) { int r = i / 10, c = i - r * 10; wf1[r * 60 + 50 + c] = 0.f; }
    for (int i = tid; i < 4096; i += 256) {
        int r = i >> 5, c = i & 31;
        *(float4*)(wf2 + r * 132 + c * 4) = *(const float4*)(Wf2 + r * 128 + c * 4);
    }
    if (tid < 128) { b1s[tid] = b1[tid]; b2s[tid] = b2[tid]; }
    for (int i = tid; i < 640; i += 256) { int r = i / 10, c = i - r * 10; fjs[r * 60 + 50 + c] = 0.f; }

    for (int at = 0; at < 8; ++at) {
        int atom = blockIdx.x * 8 + at;
        __syncthreads();
        const float* fb = fij + (size_t)atom * 3200;
        for (int i = tid; i < 3200; i += 256) { int r = i / 50, c = i - r * 50; fjs[r * 60 + c] = fb[i]; }
        if (tid < 64) {
            cms[tid] = (rij[(size_t)atom * 64 + tid] <= 5.0f) ? nmask[(size_t)atom * 64 + tid] : 0.f;
            nbs[tid] = nbrs[(size_t)atom * 64 + tid];
        }
        __syncthreads();
        {   // GEMM1 (K=50 padded to 56) + ssp -> w1s
            float a1[8][4]{};
#pragma unroll
            for (int ks = 0; ks < 7; ++ks)
                gstep<8>(fjs, 60, wm * 16, ks * 8, wf1, 60, wn * 64, lane, a1);
            int r0 = wm * 16 + g;
#pragma unroll
            for (int j = 0; j < 8; ++j) {
                int n0 = wn * 64 + j * 8 + 2 * t;
                float bb0 = b1s[n0], bb1 = b1s[n0 + 1];
                *(float2*)(w1s + r0 * 132 + n0) =
                    make_float2(sspf(a1[j][0] + bb0), sspf(a1[j][1] + bb1));
                *(float2*)(w1s + (r0 + 8) * 132 + n0) =
                    make_float2(sspf(a1[j][2] + bb0), sspf(a1[j][3] + bb1));
            }
        }
        __syncthreads();
        {   // GEMM2 (K=128) + b2, * cutoff*mask -> wts
            float a2[8][4]{};
#pragma unroll
            for (int ks = 0; ks < 16; ++ks)
                gstep<8>(w1s, 132, wm * 16, ks * 8, wf2, 132, wn * 64, lane, a2);
            int r0 = wm * 16 + g, r1 = r0 + 8;
            float c0 = cms[r0], c1 = cms[r1];
#pragma unroll
            for (int j = 0; j < 8; ++j) {
                int n0 = wn * 64 + j * 8 + 2 * t;
                float bb0 = b2s[n0], bb1 = b2s[n0 + 1];
                *(float2*)(wts + r0 * 132 + n0) =
                    make_float2((a2[j][0] + bb0) * c0, (a2[j][1] + bb1) * c0);
                *(float2*)(wts + r1 * 132 + n0) =
                    make_float2((a2[j][2] + bb0) * c1, (a2[j][3] + bb1) * c1);
            }
        }
        __syncthreads();
        {   // gather + reduce over 64 neighbors
            int f = tid & 127, h = tid >> 7;
            const float* yb = Y + (size_t)(atom & ~1023) * 128;
            float s = 0.f;
            for (int n = h * 32; n < h * 32 + 32; ++n)
                s += wts[n * 132 + f] * yb[(size_t)nbs[n] * 128 + f];
            prs[h * 128 + f] = s;
            __syncthreads();
            if (tid < 128) V[(size_t)atom * 128 + tid] = prs[tid] + prs[128 + tid];
        }
    }
}

extern "C" void kernel_launch(void* const* d_in, const int* in_sizes, int n_in,
                              void* d_out, int out_size) {
    const float* x      = (const float*)d_in[0];
    const float* rij    = (const float*)d_in[1];
    const int*   nbrs   = (const int*)d_in[2];
    const float* nmask  = (const float*)d_in[3];
    const float* fij    = (const float*)d_in[4];
    const float* Win2f  = (const float*)d_in[5];
    const float* Wf1    = (const float*)d_in[6];
    const float* bf1    = (const float*)d_in[7];
    const float* Wf2    = (const float*)d_in[8];
    const float* bf2    = (const float*)d_in[9];
    const float* Wfout  = (const float*)d_in[10];
    const float* bfout  = (const float*)d_in[11];
    const float* Wdense = (const float*)d_in[12];
    const float* bdense = (const float*)d_in[13];
    float* out = (float*)d_out;

    cudaFuncSetAttribute(gemm64_kernel, cudaFuncAttributeMaxDynamicSharedMemorySize, 101376);
    cudaFuncSetAttribute(main_kernel,  cudaFuncAttributeMaxDynamicSharedMemorySize, 183808);

    void *py, *pv, *pv2;
    cudaGetSymbolAddress(&py,  g_y);
    cudaGetSymbolAddress(&pv,  g_v);
    cudaGetSymbolAddress(&pv2, g_v2);

    gemm64_kernel<<<128, 256, 101376>>>(x, Win2f, nullptr, (float*)py, 0);
    main_kernel<<<1024, 256, 183808>>>(fij, rij, nbrs, nmask, bf1, bf2, Wf1, Wf2,
                                       (const float*)py, (float*)pv);
    // reference: v = ssp(ssp(v @ W_f2out^T + b_f2out))  <-- DOUBLE ssp
    gemm64_kernel<<<128, 256, 101376>>>((const float*)pv, Wfout, bfout, (float*)pv2, 2);
    gemm64_kernel<<<128, 256, 101376>>>((const float*)pv2, Wdense, bdense, out, 0);
}

// round 7
// speedup vs baseline: 1.5834x; 1.5834x over previous
#include <cuda_runtime.h>
#include <cstdint>

__device__ float g_y[8192*128], g_v[8192*128], g_v2[8192*128];
__device__ float g_wf1p[4*16*32*4], g_wf2p[8*16*32*4];

// ---------- tf32x3 (verified; used by gemm64_kernel) ----------
__device__ __forceinline__ void sp32(float x, uint32_t& h, uint32_t& l) {
    asm("cvt.rna.tf32.f32 %0, %1;" : "=r"(h) : "f"(x));
    float r = x - __uint_as_float(h);
    asm("cvt.rna.tf32.f32 %0, %1;" : "=r"(l) : "f"(r));
}
__device__ __forceinline__ void mma8(float* c, const uint32_t* a, uint32_t b0, uint32_t b1) {
    asm volatile("mma.sync.aligned.m16n8k8.row.col.f32.tf32.tf32.f32 "
        "{%0,%1,%2,%3},{%4,%5,%6,%7},{%8,%9},{%0,%1,%2,%3};"
        : "+f"(c[0]), "+f"(c[1]), "+f"(c[2]), "+f"(c[3])
        : "r"(a[0]), "r"(a[1]), "r"(a[2]), "r"(a[3]), "r"(b0), "r"(b1));
}
__device__ __forceinline__ float sspf(float x) {
    return fmaxf(x, 0.f) + log1pf(__expf(-fabsf(x))) - 0.69314718055994531f;
}
template <int NBLK>
__device__ __forceinline__ void gstep(const float* As, int lda, int m0, int k0,
                                      const float* Ws, int ldb, int n0, int lane,
                                      float (*acc)[4]) {
    int g = lane >> 2, t = lane & 3;
    const float* p0 = As + (m0 + g) * lda + k0 + t;
    const float* p1 = p0 + 8 * lda;
    uint32_t ah[4], al[4];
    sp32(p0[0], ah[0], al[0]); sp32(p1[0], ah[1], al[1]);
    sp32(p0[4], ah[2], al[2]); sp32(p1[4], ah[3], al[3]);
#pragma unroll
    for (int j = 0; j < NBLK; ++j) {
        const float* w = Ws + (n0 + j * 8 + g) * ldb + k0 + t;
        uint32_t bh0, bl0, bh1, bl1;
        sp32(w[0], bh0, bl0); sp32(w[4], bh1, bl1);
        mma8(acc[j], ah, bh0, bh1);
        mma8(acc[j], ah, bl0, bl1);
        mma8(acc[j], al, bh0, bh1);
    }
}

// ---------- bf16x3 helpers (main kernel) ----------
__device__ __forceinline__ uint32_t pkbf(float lo, float hi) {
    uint32_t r; asm("cvt.rn.bf16x2.f32 %0, %1, %2;" : "=r"(r) : "f"(hi), "f"(lo)); return r;
}
__device__ __forceinline__ void bsplit(float x0, float x1, uint32_t& h, uint32_t& l) {
    h = pkbf(x0, x1);
    float r0 = x0 - __uint_as_float(h << 16);
    float r1 = x1 - __uint_as_float(h & 0xffff0000u);
    l = pkbf(r0, r1);
}
__device__ __forceinline__ void mma16(float* c, const uint32_t* a, uint32_t b0, uint32_t b1) {
    asm volatile("mma.sync.aligned.m16n8k16.row.col.f32.bf16.bf16.f32 "
        "{%0,%1,%2,%3},{%4,%5,%6,%7},{%8,%9},{%0,%1,%2,%3};"
        : "+f"(c[0]), "+f"(c[1]), "+f"(c[2]), "+f"(c[3])
        : "r"(a[0]), "r"(a[1]), "r"(a[2]), "r"(a[3]), "r"(b0), "r"(b1));
}
// 2 m-tiles x NB n-blocks, one K=16 step, bf16x3, packed B fragments
template <int NB>
__device__ __forceinline__ void bstep(const float* As, int lda, int m0, int k0,
                                      const float4* Bs, int boff, int lane,
                                      float (*acc)[8][4]) {
    int g = lane >> 2, t = lane & 3;
    uint32_t ah[2][4], al[2][4];
#pragma unroll
    for (int mt = 0; mt < 2; ++mt) {
        const float* p = As + (m0 + mt * 16 + g) * lda + k0 + 2 * t;
        float2 v0 = *(const float2*)p;
        float2 v1 = *(const float2*)(p + 8 * lda);
        float2 v2 = *(const float2*)(p + 8);
        float2 v3 = *(const float2*)(p + 8 * lda + 8);
        bsplit(v0.x, v0.y, ah[mt][0], al[mt][0]);
        bsplit(v1.x, v1.y, ah[mt][1], al[mt][1]);
        bsplit(v2.x, v2.y, ah[mt][2], al[mt][2]);
        bsplit(v3.x, v3.y, ah[mt][3], al[mt][3]);
    }
#pragma unroll
    for (int j = 0; j < NB; ++j) {
        float4 b = Bs[boff + j * 32 + lane];
        uint32_t bh0 = __float_as_uint(b.x), bl0 = __float_as_uint(b.y);
        uint32_t bh1 = __float_as_uint(b.z), bl1 = __float_as_uint(b.w);
#pragma unroll
        for (int mt = 0; mt < 2; ++mt) {
            mma16(acc[mt][j], ah[mt], bh0, bh1);
            mma16(acc[mt][j], ah[mt], bl0, bl1);
            mma16(acc[mt][j], al[mt], bh0, bh1);
        }
    }
}

// ---------- pack Wf1/Wf2 into bf16 hi/lo fragment buffers ----------
__global__ void pack_kernel(const float* __restrict__ Wf1, const float* __restrict__ Wf2,
                            float4* o1, float4* o2) {
    int b = blockIdx.x, lane = threadIdx.x;
    const float* W; float4* D; int K, ks, nb;
    if (b < 64) { W = Wf1; D = o1; K = 50;  ks = b >> 4; nb = b & 15; }
    else { b -= 64; W = Wf2; D = o2; K = 128; ks = b >> 4; nb = b & 15; }
    int g = lane >> 2, t = lane & 3, n = nb * 8 + g, k0 = ks * 16 + 2 * t;
    float w0 = (k0 < K) ? W[n * K + k0] : 0.f, w1 = (k0 + 1 < K) ? W[n * K + k0 + 1] : 0.f;
    float w2 = (k0 + 8 < K) ? W[n * K + k0 + 8] : 0.f, w3 = (k0 + 9 < K) ? W[n * K + k0 + 9] : 0.f;
    uint32_t h0, l0, h1, l1;
    bsplit(w0, w1, h0, l0); bsplit(w2, w3, h1, l1);
    D[(ks * 16 + nb) * 32 + lane] = make_float4(__uint_as_float(h0), __uint_as_float(l0),
                                                __uint_as_float(h1), __uint_as_float(l1));
}

// ---------- gemm64 (verified tf32x3; doSsp = #ssp applications) ----------
__global__ __launch_bounds__(256, 1)
void gemm64_kernel(const float* __restrict__ A, const float* __restrict__ W,
                   const float* __restrict__ bias, float* __restrict__ out, int doSsp) {
    extern __shared__ __align__(16) float sm[];
    float* ws = sm;          // 128 x 132
    float* xs = sm + 16896;  // 64 x 132
    int tid = threadIdx.x, lane = tid & 31, warp = tid >> 5;
    int wm = warp & 3, wn = warp >> 2, g = lane >> 2, t = lane & 3;
    int row0 = blockIdx.x * 64;
    for (int i = tid; i < 4096; i += 256) {
        int r = i >> 5, c = i & 31;
        *(float4*)(ws + r * 132 + c * 4) = *(const float4*)(W + r * 128 + c * 4);
    }
    for (int i = tid; i < 2048; i += 256) {
        int r = i >> 5, c = i & 31;
        *(float4*)(xs + r * 132 + c * 4) = *(const float4*)(A + (size_t)(row0 + r) * 128 + c * 4);
    }
    __syncthreads();
    float acc[8][4]{};
#pragma unroll
    for (int ks = 0; ks < 16; ++ks)
        gstep<8>(xs, 132, wm * 16, ks * 8, ws, 132, wn * 64, lane, acc);
    int r0 = row0 + wm * 16 + g, r1 = r0 + 8;
#pragma unroll
    for (int j = 0; j < 8; ++j) {
        int n0 = wn * 64 + j * 8 + 2 * t;
        float b0 = bias ? bias[n0] : 0.f, b1 = bias ? bias[n0 + 1] : 0.f;
        float v00 = acc[j][0] + b0, v01 = acc[j][1] + b1;
        float v10 = acc[j][2] + b0, v11 = acc[j][3] + b1;
        for (int s = 0; s < doSsp; ++s) {
            v00 = sspf(v00); v01 = sspf(v01); v10 = sspf(v10); v11 = sspf(v11);
        }
        *(float2*)(out + (size_t)r0 * 128 + n0) = make_float2(v00, v01);
        *(float2*)(out + (size_t)r1 * 128 + n0) = make_float2(v10, v11);
    }
}

// ---------- fused main kernel v2: 2 atoms/iter, bf16x3, packed B ----------
__global__ __launch_bounds__(256, 1)
void main2(const float* __restrict__ fij, const float* __restrict__ rij,
           const int* __restrict__ nbrs, const float* __restrict__ nmask,
           const float* __restrict__ b1, const float* __restrict__ b2,
           const float4* __restrict__ wf1p, const float4* __restrict__ wf2p,
           const float* __restrict__ Y, float* __restrict__ V) {
    extern __shared__ __align__(16) float sm[];
    float4* w1p = (float4*)sm;            // 2048 float4
    float4* w2p = (float4*)(sm + 8192);   // 4096 float4
    float* fjs = sm + 24576;              // 128 x 68 (cols 50..63 zero)
    float* w1s = sm + 33280;              // 128 x 132
    float* cms = sm + 50176;              // 128
    int*   nbs = (int*)(sm + 50304);      // 128
    float* b1s = sm + 50432;              // 128
    float* b2s = sm + 50560;              // 128
    float* vps = sm + 50688;              // 4 x 128
    int tid = threadIdx.x, lane = tid & 31, warp = tid >> 5;
    int wm = warp & 3, wn = warp >> 2, g = lane >> 2, t = lane & 3;

    for (int i = tid; i < 2048; i += 256) w1p[i] = wf1p[i];
    for (int i = tid; i < 4096; i += 256) w2p[i] = wf2p[i];
    if (tid < 128) { b1s[tid] = b1[tid]; b2s[tid] = b2[tid]; }
    for (int i = tid; i < 128 * 14; i += 256) { int r = i / 14, c = i - r * 14; fjs[r * 68 + 50 + c] = 0.f; }

    for (int at = 0; at < 4; ++at) {
        int ab = blockIdx.x * 8 + at * 2;     // atom pair base
        __syncthreads();
        const float* fb = fij + (size_t)ab * 3200;
        for (int i = tid; i < 6400; i += 256) { int r = i / 50, c = i - r * 50; fjs[r * 68 + c] = fb[i]; }
        if (tid < 128) {
            cms[tid] = (rij[(size_t)ab * 64 + tid] <= 5.0f) ? nmask[(size_t)ab * 64 + tid] : 0.f;
            nbs[tid] = nbrs[(size_t)ab * 64 + tid];
        }
        __syncthreads();
        {   // GEMM1 (K=64 padded) + b1 + ssp -> w1s
            float a1[2][8][4]{};
#pragma unroll
            for (int ks = 0; ks < 4; ++ks)
                bstep<8>(fjs, 68, wm * 32, ks * 16, w1p, (ks * 16 + wn * 8) * 32, lane, a1);
#pragma unroll
            for (int mt = 0; mt < 2; ++mt) {
                int r0 = wm * 32 + mt * 16 + g;
#pragma unroll
                for (int j = 0; j < 8; ++j) {
                    int c = wn * 64 + j * 8 + 2 * t;
                    float bb0 = b1s[c], bb1 = b1s[c + 1];
                    *(float2*)(w1s + r0 * 132 + c) =
                        make_float2(sspf(a1[mt][j][0] + bb0), sspf(a1[mt][j][1] + bb1));
                    *(float2*)(w1s + (r0 + 8) * 132 + c) =
                        make_float2(sspf(a1[mt][j][2] + bb0), sspf(a1[mt][j][3] + bb1));
                }
            }
        }
        __syncthreads();
        {   // GEMM2 (K=128) + b2, *cm, gather y, reduce rows -> vps
            float a2[2][8][4]{};
#pragma unroll
            for (int ks = 0; ks < 8; ++ks)
                bstep<8>(w1s, 132, wm * 32, ks * 16, w2p, (ks * 16 + wn * 8) * 32, lane, a2);
            int atom = ab + (wm >> 1);
            const float* yb = Y + (size_t)((atom >> 10) << 10) * 128;
            float2 p[8];
#pragma unroll
            for (int j = 0; j < 8; ++j) p[j] = make_float2(0.f, 0.f);
#pragma unroll
            for (int mt = 0; mt < 2; ++mt)
#pragma unroll
                for (int ri = 0; ri < 2; ++ri) {
                    int r = wm * 32 + mt * 16 + ri * 8 + g;
                    float cm = cms[r];
                    const float* yr = yb + (size_t)nbs[r] * 128;
#pragma unroll
                    for (int j = 0; j < 8; ++j) {
                        int c = wn * 64 + j * 8 + 2 * t;
                        float2 yv = *(const float2*)(yr + c);
                        float w0 = (a2[mt][j][ri * 2 + 0] + b2s[c]) * cm;
                        float w1v = (a2[mt][j][ri * 2 + 1] + b2s[c + 1]) * cm;
                        p[j].x += w0 * yv.x; p[j].y += w1v * yv.y;
                    }
                }
#pragma unroll
            for (int j = 0; j < 8; ++j)
#pragma unroll
                for (int off = 16; off >= 4; off >>= 1) {
                    p[j].x += __shfl_down_sync(0xffffffffu, p[j].x, off);
                    p[j].y += __shfl_down_sync(0xffffffffu, p[j].y, off);
                }
            if (lane < 4)
#pragma unroll
                for (int j = 0; j < 8; ++j)
                    *(float2*)(vps + wm * 128 + wn * 64 + j * 8 + 2 * lane) = p[j];
        }
        __syncthreads();
        V[(size_t)ab * 128 + tid] =
            vps[(tid >> 7) * 256 + (tid & 127)] + vps[(tid >> 7) * 256 + 128 + (tid & 127)];
    }
}

extern "C" void kernel_launch(void* const* d_in, const int* in_sizes, int n_in,
                              void* d_out, int out_size) {
    const float* x      = (const float*)d_in[0];
    const float* rij    = (const float*)d_in[1];
    const int*   nbrs   = (const int*)d_in[2];
    const float* nmask  = (const float*)d_in[3];
    const float* fij    = (const float*)d_in[4];
    const float* Win2f  = (const float*)d_in[5];
    const float* Wf1    = (const float*)d_in[6];
    const float* bf1    = (const float*)d_in[7];
    const float* Wf2    = (const float*)d_in[8];
    const float* bf2    = (const float*)d_in[9];
    const float* Wfout  = (const float*)d_in[10];
    const float* bfout  = (const float*)d_in[11];
    const float* Wdense = (const float*)d_in[12];
    const float* bdense = (const float*)d_in[13];
    float* out = (float*)d_out;

    cudaFuncSetAttribute(gemm64_kernel, cudaFuncAttributeMaxDynamicSharedMemorySize, 101376);
    cudaFuncSetAttribute(main2, cudaFuncAttributeMaxDynamicSharedMemorySize, 204800);

    void *py, *pv, *pv2, *p1, *p2;
    cudaGetSymbolAddress(&py, g_y);
    cudaGetSymbolAddress(&pv, g_v);
    cudaGetSymbolAddress(&pv2, g_v2);
    cudaGetSymbolAddress(&p1, g_wf1p);
    cudaGetSymbolAddress(&p2, g_wf2p);

    pack_kernel<<<192, 32>>>(Wf1, Wf2, (float4*)p1, (float4*)p2);
    gemm64_kernel<<<128, 256, 101376>>>(x, Win2f, nullptr, (float*)py, 0);
    main2<<<1024, 256, 204800>>>(fij, rij, nbrs, nmask, bf1, bf2,
                                 (const float4*)p1, (const float4*)p2,
                                 (const float*)py, (float*)pv);
    gemm64_kernel<<<128, 256, 101376>>>((const float*)pv, Wfout, bfout, (float*)pv2, 2);
    gemm64_kernel<<<128, 256, 101376>>>((const float*)pv2, Wdense, bdense, out, 0);
}

// round 8
// speedup vs baseline: 1.6553x; 1.0454x over previous
#include <cuda_runtime.h>
#include <cstdint>

typedef unsigned long long u64;

__device__ float g_y[8192*128], g_v[8192*128], g_v2[8192*128];
__device__ float4 g_wp0[8*16*32], g_wp1[4*16*32], g_wp2[8*16*32],
                  g_wp3[8*16*32], g_wp4[8*16*32];

__device__ __forceinline__ uint32_t pkbf(float lo, float hi) {
    uint32_t r; asm("cvt.rn.bf16x2.f32 %0, %1, %2;" : "=r"(r) : "f"(hi), "f"(lo)); return r;
}
__device__ __forceinline__ void bsplit(float x0, float x1, uint32_t& h, uint32_t& l) {
    h = pkbf(x0, x1);
    float r0 = x0 - __uint_as_float(h << 16);
    float r1 = x1 - __uint_as_float(h & 0xffff0000u);
    l = pkbf(r0, r1);
}
__device__ __forceinline__ void mma16(float* c, const uint32_t* a, uint32_t b0, uint32_t b1) {
    asm volatile("mma.sync.aligned.m16n8k16.row.col.f32.bf16.bf16.f32 "
        "{%0,%1,%2,%3},{%4,%5,%6,%7},{%8,%9},{%0,%1,%2,%3};"
        : "+f"(c[0]), "+f"(c[1]), "+f"(c[2]), "+f"(c[3])
        : "r"(a[0]), "r"(a[1]), "r"(a[2]), "r"(a[3]), "r"(b0), "r"(b1));
}
__device__ __forceinline__ float sspf(float x) {
    return fmaxf(x, 0.f) + log1pf(__expf(-fabsf(x))) - 0.69314718055994531f;
}

// packed-A K=16 step: A smem uint2 (hi,lo bf16x2 per k-pair), B packed float4 frags
template <int MT, int NB>
__device__ __forceinline__ void pstep(const uint2* Ap, int lda, int m0, int kc,
                                      const float4* Bs, int lane, float (*acc)[NB][4]) {
    int g = lane >> 2, t = lane & 3;
    uint32_t ah[MT][4], al[MT][4];
#pragma unroll
    for (int mt = 0; mt < MT; ++mt) {
        const uint2* p0 = Ap + (m0 + mt * 16 + g) * lda + kc + t;
        const uint2* p1 = p0 + 8 * lda;
        uint2 a0 = p0[0], a1 = p1[0], a2 = p0[4], a3 = p1[4];
        ah[mt][0] = a0.x; al[mt][0] = a0.y; ah[mt][1] = a1.x; al[mt][1] = a1.y;
        ah[mt][2] = a2.x; al[mt][2] = a2.y; ah[mt][3] = a3.x; al[mt][3] = a3.y;
    }
#pragma unroll
    for (int j = 0; j < NB; ++j) {
        float4 b = Bs[j * 32 + lane];
        uint32_t bh0 = __float_as_uint(b.x), bl0 = __float_as_uint(b.y);
        uint32_t bh1 = __float_as_uint(b.z), bl1 = __float_as_uint(b.w);
#pragma unroll
        for (int mt = 0; mt < MT; ++mt) {
            mma16(acc[mt][j], ah[mt], bh0, bh1);
            mma16(acc[mt][j], ah[mt], bl0, bl1);
            mma16(acc[mt][j], al[mt], bh0, bh1);
        }
    }
}

// pack all 5 weight matrices into bf16 hi/lo fragment buffers (validated format)
__global__ void pack5(const float* w0, const float* w1, const float* w2,
                      const float* w3, const float* w4,
                      float4* o0, float4* o1, float4* o2, float4* o3, float4* o4) {
    int b = blockIdx.x, lane = threadIdx.x, kidx = b >> 4, nb = b & 15;
    const float* W; float4* D; int K, ks;
    if (kidx < 8)       { W = w0; D = o0; K = 128; ks = kidx;      }
    else if (kidx < 12) { W = w1; D = o1; K = 50;  ks = kidx - 8;  }
    else if (kidx < 20) { W = w2; D = o2; K = 128; ks = kidx - 12; }
    else if (kidx < 28) { W = w3; D = o3; K = 128; ks = kidx - 20; }
    else                { W = w4; D = o4; K = 128; ks = kidx - 28; }
    int g = lane >> 2, t = lane & 3, n = nb * 8 + g, k0 = ks * 16 + 2 * t;
    float a = (k0 < K) ? W[n * K + k0] : 0.f, b1 = (k0 + 1 < K) ? W[n * K + k0 + 1] : 0.f;
    float c = (k0 + 8 < K) ? W[n * K + k0 + 8] : 0.f, d = (k0 + 9 < K) ? W[n * K + k0 + 9] : 0.f;
    uint32_t h0, l0, h1, l1;
    bsplit(a, b1, h0, l0); bsplit(c, d, h1, l1);
    D[(ks * 16 + nb) * 32 + lane] = make_float4(__uint_as_float(h0), __uint_as_float(l0),
                                                __uint_as_float(h1), __uint_as_float(l1));
}

// out[8192,128] = ssp^nssp(A[8192,128] @ W^T + bias), bf16x3, packed operands
__global__ __launch_bounds__(512, 2)
void gemmB(const float* __restrict__ A, const float4* __restrict__ Bp,
           const float* __restrict__ bias, float* __restrict__ out, int nssp) {
    extern __shared__ __align__(16) float sm[];
    float4* bf = (float4*)sm;              // 4096 float4
    uint2*  ap = (uint2*)(sm + 16384);     // 64 x 68
    int tid = threadIdx.x, lane = tid & 31, warp = tid >> 5;
    int wm = warp & 3, wn = warp >> 2, g = lane >> 2, t = lane & 3;
    int row0 = blockIdx.x * 64;
    for (int i = tid; i < 4096; i += 512) bf[i] = Bp[i];
    for (int i = tid; i < 4096; i += 512) {
        int r = i >> 6, cp = i & 63;
        float2 v = *(const float2*)(A + (size_t)(row0 + r) * 128 + 2 * cp);
        uint32_t h, l; bsplit(v.x, v.y, h, l);
        ap[r * 68 + cp] = make_uint2(h, l);
    }
    __syncthreads();
    float acc[1][4][4]{};
#pragma unroll
    for (int ks = 0; ks < 8; ++ks)
        pstep<1, 4>(ap, 68, wm * 16, ks * 8, bf + (ks * 16 + wn * 4) * 32, lane, acc);
    int r0 = row0 + wm * 16 + g, r1 = r0 + 8;
#pragma unroll
    for (int j = 0; j < 4; ++j) {
        int c = wn * 32 + j * 8 + 2 * t;
        float b0 = bias ? bias[c] : 0.f, b1 = bias ? bias[c + 1] : 0.f;
        float v00 = acc[0][j][0] + b0, v01 = acc[0][j][1] + b1;
        float v10 = acc[0][j][2] + b0, v11 = acc[0][j][3] + b1;
        for (int s = 0; s < nssp; ++s) {
            v00 = sspf(v00); v01 = sspf(v01); v10 = sspf(v10); v11 = sspf(v11);
        }
        *(float2*)(out + (size_t)r0 * 128 + c) = make_float2(v00, v01);
        *(float2*)(out + (size_t)r1 * 128 + c) = make_float2(v10, v11);
    }
}

// fused main: 512 thr, 2 atoms/iter (M=128), packed-A bf16x3 both GEMMs
__global__ __launch_bounds__(512, 1)
void main3(const float* __restrict__ fij, const float* __restrict__ rij,
           const int* __restrict__ nbrs, const float* __restrict__ nmask,
           const float* __restrict__ b1, const float* __restrict__ b2,
           const float4* __restrict__ w1g, const float4* __restrict__ w2g,
           const float* __restrict__ Y, float* __restrict__ V) {
    extern __shared__ __align__(16) float sm[];
    float4* b1f = (float4*)sm;              // 2048 float4
    float4* b2f = (float4*)(sm + 8192);     // 4096 float4
    uint2*  fjs = (uint2*)(sm + 24576);     // 128 x 36 (pairs; 25..31 zero)
    uint2*  w1p = (uint2*)(sm + 33792);     // 128 x 68
    float* cms = sm + 51200; int* nbs = (int*)(sm + 51328);
    float* b1s = sm + 51456; float* b2s = sm + 51584; float* vps = sm + 51712; // 512
    int tid = threadIdx.x, lane = tid & 31, warp = tid >> 5;
    int wm = warp & 3, wn = warp >> 2, g = lane >> 2, t = lane & 3;

    for (int i = tid; i < 2048; i += 512) b1f[i] = w1g[i];
    for (int i = tid; i < 4096; i += 512) b2f[i] = w2g[i];
    if (tid < 128) { b1s[tid] = b1[tid]; b2s[tid] = b2[tid]; }
    for (int i = tid; i < 896; i += 512) {
        int r = i / 7, c = 25 + (i - r * 7);
        fjs[r * 36 + c] = make_uint2(0u, 0u);
    }

    for (int at = 0; at < 4; ++at) {
        int ab = blockIdx.x * 8 + at * 2;
        __syncthreads();
        const float* fb = fij + (size_t)ab * 3200;
        for (int i = tid; i < 3200; i += 512) {
            int r = i / 25, cp = i - r * 25;
            float2 v = *(const float2*)(fb + r * 50 + 2 * cp);
            uint32_t h, l; bsplit(v.x, v.y, h, l);
            fjs[r * 36 + cp] = make_uint2(h, l);
        }
        if (tid < 128) {
            cms[tid] = (rij[(size_t)ab * 64 + tid] <= 5.0f) ? nmask[(size_t)ab * 64 + tid] : 0.f;
            nbs[tid] = nbrs[(size_t)ab * 64 + tid];
        }
        __syncthreads();
        {   // GEMM1 (K=64 padded) + b1 + ssp -> packed w1p
            float a1[2][4][4]{};
#pragma unroll
            for (int ks = 0; ks < 4; ++ks)
                pstep<2, 4>(fjs, 36, wm * 32, ks * 8, b1f + (ks * 16 + wn * 4) * 32, lane, a1);
#pragma unroll
            for (int mt = 0; mt < 2; ++mt) {
                int r0 = wm * 32 + mt * 16 + g;
#pragma unroll
                for (int j = 0; j < 4; ++j) {
                    int c = wn * 32 + j * 8 + 2 * t, ci = c >> 1;
                    float bb0 = b1s[c], bb1 = b1s[c + 1];
                    uint32_t h, l;
                    bsplit(sspf(a1[mt][j][0] + bb0), sspf(a1[mt][j][1] + bb1), h, l);
                    w1p[r0 * 68 + ci] = make_uint2(h, l);
                    bsplit(sspf(a1[mt][j][2] + bb0), sspf(a1[mt][j][3] + bb1), h, l);
                    w1p[(r0 + 8) * 68 + ci] = make_uint2(h, l);
                }
            }
        }
        __syncthreads();
        {   // GEMM2 (K=128) + b2, *cm, gather y, reduce rows
            float a2[2][4][4]{};
#pragma unroll
            for (int ks = 0; ks < 8; ++ks)
                pstep<2, 4>(w1p, 68, wm * 32, ks * 8, b2f + (ks * 16 + wn * 4) * 32, lane, a2);
            const float* yb = Y + (size_t)((ab >> 10) << 10) * 128;
            float2 p[4];
#pragma unroll
            for (int j = 0; j < 4; ++j) p[j] = make_float2(0.f, 0.f);
#pragma unroll
            for (int mt = 0; mt < 2; ++mt)
#pragma unroll
                for (int ri = 0; ri < 2; ++ri) {
                    int r = wm * 32 + mt * 16 + ri * 8 + g;
                    float cm = cms[r];
                    const float* yr = yb + (size_t)nbs[r] * 128;
#pragma unroll
                    for (int j = 0; j < 4; ++j) {
                        int c = wn * 32 + j * 8 + 2 * t;
                        float2 yv = *(const float2*)(yr + c);
                        p[j].x += (a2[mt][j][ri * 2 + 0] + b2s[c]) * cm * yv.x;
                        p[j].y += (a2[mt][j][ri * 2 + 1] + b2s[c + 1]) * cm * yv.y;
                    }
                }
#pragma unroll
            for (int j = 0; j < 4; ++j)
#pragma unroll
                for (int off = 16; off >= 4; off >>= 1) {
                    p[j].x += __shfl_down_sync(0xffffffffu, p[j].x, off);
                    p[j].y += __shfl_down_sync(0xffffffffu, p[j].y, off);
                }
            if (lane < 4)
#pragma unroll
                for (int j = 0; j < 4; ++j)
                    *(float2*)(vps + wm * 128 + wn * 32 + j * 8 + 2 * lane) = p[j];
        }
        __syncthreads();
        if (tid < 256) {
            int a = tid >> 7, c = tid & 127;
            V[(size_t)(ab + a) * 128 + c] = vps[a * 256 + c] + vps[a * 256 + 128 + c];
        }
    }
}

extern "C" void kernel_launch(void* const* d_in, const int* in_sizes, int n_in,
                              void* d_out, int out_size) {
    const float* x      = (const float*)d_in[0];
    const float* rij    = (const float*)d_in[1];
    const int*   nbrs   = (const int*)d_in[2];
    const float* nmask  = (const float*)d_in[3];
    const float* fij    = (const float*)d_in[4];
    const float* Win2f  = (const float*)d_in[5];
    const float* Wf1    = (const float*)d_in[6];
    const float* bf1    = (const float*)d_in[7];
    const float* Wf2    = (const float*)d_in[8];
    const float* bf2    = (const float*)d_in[9];
    const float* Wfout  = (const float*)d_in[10];
    const float* bfout  = (const float*)d_in[11];
    const float* Wdense = (const float*)d_in[12];
    const float* bdense = (const float*)d_in[13];
    float* out = (float*)d_out;

    cudaFuncSetAttribute(gemmB, cudaFuncAttributeMaxDynamicSharedMemorySize, 100352);
    cudaFuncSetAttribute(main3, cudaFuncAttributeMaxDynamicSharedMemorySize, 208896);

    void *py, *pv, *pv2, *p0, *p1, *p2, *p3, *p4;
    cudaGetSymbolAddress(&py, g_y);
    cudaGetSymbolAddress(&pv, g_v);
    cudaGetSymbolAddress(&pv2, g_v2);
    cudaGetSymbolAddress(&p0, g_wp0);
    cudaGetSymbolAddress(&p1, g_wp1);
    cudaGetSymbolAddress(&p2, g_wp2);
    cudaGetSymbolAddress(&p3, g_wp3);
    cudaGetSymbolAddress(&p4, g_wp4);

    pack5<<<576, 32>>>(Win2f, Wf1, Wf2, Wfout, Wdense,
                       (float4*)p0, (float4*)p1, (float4*)p2, (float4*)p3, (float4*)p4);
    gemmB<<<128, 512, 100352>>>(x, (const float4*)p0, nullptr, (float*)py, 0);
    main3<<<1024, 512, 208896>>>(fij, rij, nbrs, nmask, bf1, bf2,
                                 (const float4*)p1, (const float4*)p2,
                                 (const float*)py, (float*)pv);
    gemmB<<<128, 512, 100352>>>((const float*)pv, (const float4*)p3, bfout, (float*)pv2, 2);
    gemmB<<<128, 512, 100352>>>((const float*)pv2, (const float4*)p4, bdense, out, 0);
}

// round 9
// speedup vs baseline: 2.0515x; 1.2393x over previous
#include <cuda_runtime.h>
#include <cstdint>

__device__ float g_y[8192*128], g_v[8192*128];
__device__ float4 g_wp0[8*16*32], g_wp1[4*16*32], g_wp2[8*16*32],
                  g_wp3[8*16*32], g_wp4[8*16*32];

__device__ __forceinline__ uint32_t pkbf(float lo, float hi) {
    uint32_t r; asm("cvt.rn.bf16x2.f32 %0, %1, %2;" : "=r"(r) : "f"(hi), "f"(lo)); return r;
}
__device__ __forceinline__ void bsplit(float x0, float x1, uint32_t& h, uint32_t& l) {
    h = pkbf(x0, x1);
    float r0 = x0 - __uint_as_float(h << 16);
    float r1 = x1 - __uint_as_float(h & 0xffff0000u);
    l = pkbf(r0, r1);
}
__device__ __forceinline__ void mma16(float* c, const uint32_t* a, uint32_t b0, uint32_t b1) {
    asm volatile("mma.sync.aligned.m16n8k16.row.col.f32.bf16.bf16.f32 "
        "{%0,%1,%2,%3},{%4,%5,%6,%7},{%8,%9},{%0,%1,%2,%3};"
        : "+f"(c[0]), "+f"(c[1]), "+f"(c[2]), "+f"(c[3])
        : "r"(a[0]), "r"(a[1]), "r"(a[2]), "r"(a[3]), "r"(b0), "r"(b1));
}
__device__ __forceinline__ float sspf(float x) {   // fast ssp, ~2^-21 accurate
    float e = __expf(-fabsf(x));
    return fmaxf(x, 0.f) + __logf(1.f + e) - 0.69314718055994531f;
}

// one K=16 step, 16xNB*8 warp tile: A packed uint2 (hi,lo bf16x2), B packed float4
template <int NB>
__device__ __forceinline__ void pstep(const uint2* Ap, int lda, int m0, int kc,
                                      const float4* Bs, int lane, float (*acc)[4]) {
    int g = lane >> 2, t = lane & 3;
    const uint2* p0 = Ap + (m0 + g) * lda + kc + t;
    const uint2* p1 = p0 + 8 * lda;
    uint2 a0 = p0[0], a1 = p1[0], a2 = p0[4], a3 = p1[4];
    uint32_t ah[4] = {a0.x, a1.x, a2.x, a3.x};
    uint32_t al[4] = {a0.y, a1.y, a2.y, a3.y};
#pragma unroll
    for (int j = 0; j < NB; ++j) {
        float4 b = Bs[j * 32 + lane];
        uint32_t bh0 = __float_as_uint(b.x), bl0 = __float_as_uint(b.y);
        uint32_t bh1 = __float_as_uint(b.z), bl1 = __float_as_uint(b.w);
        mma16(acc[j], ah, bh0, bh1);
        mma16(acc[j], ah, bl0, bl1);
        mma16(acc[j], al, bh0, bh1);
    }
}

// pack all 5 weight matrices into bf16 hi/lo fragment buffers (validated format)
__global__ void pack5(const float* w0, const float* w1, const float* w2,
                      const float* w3, const float* w4,
                      float4* o0, float4* o1, float4* o2, float4* o3, float4* o4) {
    int b = blockIdx.x, lane = threadIdx.x, kidx = b >> 4, nb = b & 15;
    const float* W; float4* D; int K, ks;
    if (kidx < 8)       { W = w0; D = o0; K = 128; ks = kidx;      }
    else if (kidx < 12) { W = w1; D = o1; K = 50;  ks = kidx - 8;  }
    else if (kidx < 20) { W = w2; D = o2; K = 128; ks = kidx - 12; }
    else if (kidx < 28) { W = w3; D = o3; K = 128; ks = kidx - 20; }
    else                { W = w4; D = o4; K = 128; ks = kidx - 28; }
    int g = lane >> 2, t = lane & 3, n = nb * 8 + g, k0 = ks * 16 + 2 * t;
    float a = (k0 < K) ? W[n * K + k0] : 0.f, b1 = (k0 + 1 < K) ? W[n * K + k0 + 1] : 0.f;
    float c = (k0 + 8 < K) ? W[n * K + k0 + 8] : 0.f, d = (k0 + 9 < K) ? W[n * K + k0 + 9] : 0.f;
    uint32_t h0, l0, h1, l1;
    bsplit(a, b1, h0, l0); bsplit(c, d, h1, l1);
    D[(ks * 16 + nb) * 32 + lane] = make_float4(__uint_as_float(h0), __uint_as_float(l0),
                                                __uint_as_float(h1), __uint_as_float(l1));
}

// y[8192,128] = A[8192,128] @ W0^T  (64 rows/CTA, 512 thr)
__global__ __launch_bounds__(512, 1)
void gemmB(const float* __restrict__ A, const float4* __restrict__ Bp,
           float* __restrict__ out) {
    extern __shared__ __align__(16) float sm[];
    float4* bf = (float4*)sm;              // 4096
    uint2*  ap = (uint2*)(sm + 16384);     // 64 x 68
    int tid = threadIdx.x, lane = tid & 31, warp = tid >> 5;
    int wm = warp & 3, wn = warp >> 2, g = lane >> 2, t = lane & 3;
    int row0 = blockIdx.x * 64;
    for (int i = tid; i < 4096; i += 512) bf[i] = Bp[i];
    for (int i = tid; i < 4096; i += 512) {
        int r = i >> 6, cp = i & 63;
        float2 v = *(const float2*)(A + (size_t)(row0 + r) * 128 + 2 * cp);
        uint32_t h, l; bsplit(v.x, v.y, h, l);
        ap[r * 68 + cp] = make_uint2(h, l);
    }
    __syncthreads();
    float acc[4][4]{};
#pragma unroll
    for (int ks = 0; ks < 8; ++ks)
        pstep<4>(ap, 68, wm * 16, ks * 8, bf + (ks * 16 + wn * 4) * 32, lane, acc);
    int r0 = row0 + wm * 16 + g, r1 = r0 + 8;
#pragma unroll
    for (int j = 0; j < 4; ++j) {
        int c = wn * 32 + j * 8 + 2 * t;
        *(float2*)(out + (size_t)r0 * 128 + c) = make_float2(acc[j][0], acc[j][1]);
        *(float2*)(out + (size_t)r1 * 128 + c) = make_float2(acc[j][2], acc[j][3]);
    }
}

// fused tail: out = ssp(ssp(v @ W3^T + b3)) @ W4^T + b4   (64 rows/CTA)
__global__ __launch_bounds__(512, 1)
void gemmC(const float* __restrict__ A, const float4* __restrict__ B3,
           const float4* __restrict__ B4, const float* __restrict__ b3,
           const float* __restrict__ b4, float* __restrict__ out) {
    extern __shared__ __align__(16) float sm[];
    float4* f3 = (float4*)sm;               // 4096
    float4* f4 = (float4*)(sm + 16384);     // 4096
    uint2*  ap = (uint2*)(sm + 32768);      // 64 x 68
    uint2*  vp = (uint2*)(sm + 41472);      // 64 x 68
    float* b3s = sm + 50176; float* b4s = sm + 50304;
    int tid = threadIdx.x, lane = tid & 31, warp = tid >> 5;
    int wm = warp & 3, wn = warp >> 2, g = lane >> 2, t = lane & 3;
    int row0 = blockIdx.x * 64;
    for (int i = tid; i < 4096; i += 512) { f3[i] = B3[i]; f4[i] = B4[i]; }
    if (tid < 128) { b3s[tid] = b3[tid]; b4s[tid] = b4[tid]; }
    for (int i = tid; i < 4096; i += 512) {
        int r = i >> 6, cp = i & 63;
        float2 v = *(const float2*)(A + (size_t)(row0 + r) * 128 + 2 * cp);
        uint32_t h, l; bsplit(v.x, v.y, h, l);
        ap[r * 68 + cp] = make_uint2(h, l);
    }
    __syncthreads();
    float acc[4][4]{};
#pragma unroll
    for (int ks = 0; ks < 8; ++ks)
        pstep<4>(ap, 68, wm * 16, ks * 8, f3 + (ks * 16 + wn * 4) * 32, lane, acc);
    int lr0 = wm * 16 + g;
#pragma unroll
    for (int j = 0; j < 4; ++j) {
        int c = wn * 32 + j * 8 + 2 * t, ci = c >> 1;
        float bb0 = b3s[c], bb1 = b3s[c + 1];
        uint32_t h, l;
        bsplit(sspf(sspf(acc[j][0] + bb0)), sspf(sspf(acc[j][1] + bb1)), h, l);
        vp[lr0 * 68 + ci] = make_uint2(h, l);
        bsplit(sspf(sspf(acc[j][2] + bb0)), sspf(sspf(acc[j][3] + bb1)), h, l);
        vp[(lr0 + 8) * 68 + ci] = make_uint2(h, l);
    }
    __syncthreads();
    float a2[4][4]{};
#pragma unroll
    for (int ks = 0; ks < 8; ++ks)
        pstep<4>(vp, 68, wm * 16, ks * 8, f4 + (ks * 16 + wn * 4) * 32, lane, a2);
    int r0 = row0 + lr0, r1 = r0 + 8;
#pragma unroll
    for (int j = 0; j < 4; ++j) {
        int c = wn * 32 + j * 8 + 2 * t;
        float bb0 = b4s[c], bb1 = b4s[c + 1];
        *(float2*)(out + (size_t)r0 * 128 + c) = make_float2(a2[j][0] + bb0, a2[j][1] + bb1);
        *(float2*)(out + (size_t)r1 * 128 + c) = make_float2(a2[j][2] + bb0, a2[j][3] + bb1);
    }
}

// fused main: 1024 thr (32 warps), 2 atoms/iter (M=128), warp tile 16x32
__global__ __launch_bounds__(1024, 1)
void main4(const float* __restrict__ fij, const float* __restrict__ rij,
           const int* __restrict__ nbrs, const float* __restrict__ nmask,
           const float* __restrict__ b1, const float* __restrict__ b2,
           const float4* __restrict__ w1g, const float4* __restrict__ w2g,
           const float* __restrict__ Y, float* __restrict__ V) {
    extern __shared__ __align__(16) float sm[];
    float4* b1f = (float4*)sm;              // 2048
    float4* b2f = (float4*)(sm + 8192);     // 4096
    uint2*  fjs = (uint2*)(sm + 24576);     // 128 x 36 (pairs 25..31 zero)
    uint2*  w1p = (uint2*)(sm + 33792);     // 128 x 68
    float* cms = sm + 51200; int* nbs = (int*)(sm + 51328);
    float* b1s = sm + 51456; float* b2s = sm + 51584;
    float* vps = sm + 51712;                // 8 x 128
    int tid = threadIdx.x, lane = tid & 31, warp = tid >> 5;
    int wm = warp & 7, wn = warp >> 3, g = lane >> 2, t = lane & 3;

    for (int i = tid; i < 2048; i += 1024) b1f[i] = w1g[i];
    for (int i = tid; i < 4096; i += 1024) b2f[i] = w2g[i];
    if (tid < 128) { b1s[tid] = b1[tid]; b2s[tid] = b2[tid]; }
    if (tid < 896) { int r = tid / 7, c = 25 + (tid - r * 7); fjs[r * 36 + c] = make_uint2(0u, 0u); }

    for (int at = 0; at < 4; ++at) {
        int ab = blockIdx.x * 8 + at * 2;
        __syncthreads();
        const float* fb = fij + (size_t)ab * 3200;
        for (int i = tid; i < 3200; i += 1024) {
            int r = i / 25, cp = i - r * 25;
            float2 v = *(const float2*)(fb + r * 50 + 2 * cp);
            uint32_t h, l; bsplit(v.x, v.y, h, l);
            fjs[r * 36 + cp] = make_uint2(h, l);
        }
        if (tid < 128) {
            cms[tid] = (rij[(size_t)ab * 64 + tid] <= 5.0f) ? nmask[(size_t)ab * 64 + tid] : 0.f;
            nbs[tid] = nbrs[(size_t)ab * 64 + tid];
        }
        __syncthreads();
        {   // GEMM1 (K=64 padded) + b1 + ssp -> packed w1p
            float a1[4][4]{};
#pragma unroll
            for (int ks = 0; ks < 4; ++ks)
                pstep<4>(fjs, 36, wm * 16, ks * 8, b1f + (ks * 16 + wn * 4) * 32, lane, a1);
            int r0 = wm * 16 + g;
#pragma unroll
            for (int j = 0; j < 4; ++j) {
                int c = wn * 32 + j * 8 + 2 * t, ci = c >> 1;
                float bb0 = b1s[c], bb1 = b1s[c + 1];
                uint32_t h, l;
                bsplit(sspf(a1[j][0] + bb0), sspf(a1[j][1] + bb1), h, l);
                w1p[r0 * 68 + ci] = make_uint2(h, l);
                bsplit(sspf(a1[j][2] + bb0), sspf(a1[j][3] + bb1), h, l);
                w1p[(r0 + 8) * 68 + ci] = make_uint2(h, l);
            }
        }
        __syncthreads();
        {   // GEMM2 (K=128) + b2, *cm, gather y, reduce
            float a2[4][4]{};
#pragma unroll
            for (int ks = 0; ks < 8; ++ks)
                pstep<4>(w1p, 68, wm * 16, ks * 8, b2f + (ks * 16 + wn * 4) * 32, lane, a2);
            const float* yb = Y + (size_t)((ab >> 10) << 10) * 128;
            int r0 = wm * 16 + g, r1 = r0 + 8;
            float cm0 = cms[r0], cm1 = cms[r1];
            const float* y0 = yb + (size_t)nbs[r0] * 128;
            const float* y1 = yb + (size_t)nbs[r1] * 128;
            float2 p[4];
#pragma unroll
            for (int j = 0; j < 4; ++j) {
                int c = wn * 32 + j * 8 + 2 * t;
                float2 ya = *(const float2*)(y0 + c);
                float2 yc = *(const float2*)(y1 + c);
                float bb0 = b2s[c], bb1 = b2s[c + 1];
                p[j].x = (a2[j][0] + bb0) * cm0 * ya.x + (a2[j][2] + bb0) * cm1 * yc.x;
                p[j].y = (a2[j][1] + bb1) * cm0 * ya.y + (a2[j][3] + bb1) * cm1 * yc.y;
            }
#pragma unroll
            for (int j = 0; j < 4; ++j)
#pragma unroll
                for (int off = 16; off >= 4; off >>= 1) {
                    p[j].x += __shfl_down_sync(0xffffffffu, p[j].x, off);
                    p[j].y += __shfl_down_sync(0xffffffffu, p[j].y, off);
                }
            if (lane < 4)
#pragma unroll
                for (int j = 0; j < 4; ++j)
                    *(float2*)(vps + wm * 128 + wn * 32 + j * 8 + 2 * lane) = p[j];
        }
        __syncthreads();
        if (tid < 256) {
            int a = tid >> 7, c = tid & 127;
            float s = 0.f;
#pragma unroll
            for (int k = 0; k < 4; ++k) s += vps[(a * 4 + k) * 128 + c];
            V[(size_t)(ab + a) * 128 + c] = s;
        }
    }
}

extern "C" void kernel_launch(void* const* d_in, const int* in_sizes, int n_in,
                              void* d_out, int out_size) {
    const float* x      = (const float*)d_in[0];
    const float* rij    = (const float*)d_in[1];
    const int*   nbrs   = (const int*)d_in[2];
    const float* nmask  = (const float*)d_in[3];
    const float* fij    = (const float*)d_in[4];
    const float* Win2f  = (const float*)d_in[5];
    const float* Wf1    = (const float*)d_in[6];
    const float* bf1    = (const float*)d_in[7];
    const float* Wf2    = (const float*)d_in[8];
    const float* bf2    = (const float*)d_in[9];
    const float* Wfout  = (const float*)d_in[10];
    const float* bfout  = (const float*)d_in[11];
    const float* Wdense = (const float*)d_in[12];
    const float* bdense = (const float*)d_in[13];
    float* out = (float*)d_out;

    cudaFuncSetAttribute(gemmB, cudaFuncAttributeMaxDynamicSharedMemorySize, 100352);
    cudaFuncSetAttribute(gemmC, cudaFuncAttributeMaxDynamicSharedMemorySize, 202752);
    cudaFuncSetAttribute(main4, cudaFuncAttributeMaxDynamicSharedMemorySize, 210944);

    void *py, *pv, *p0, *p1, *p2, *p3, *p4;
    cudaGetSymbolAddress(&py, g_y);
    cudaGetSymbolAddress(&pv, g_v);
    cudaGetSymbolAddress(&p0, g_wp0);
    cudaGetSymbolAddress(&p1, g_wp1);
    cudaGetSymbolAddress(&p2, g_wp2);
    cudaGetSymbolAddress(&p3, g_wp3);
    cudaGetSymbolAddress(&p4, g_wp4);

    pack5<<<576, 32>>>(Win2f, Wf1, Wf2, Wfout, Wdense,
                       (float4*)p0, (float4*)p1, (float4*)p2, (float4*)p3, (float4*)p4);
    gemmB<<<128, 512, 100352>>>(x, (const float4*)p0, (float*)py);
    main4<<<1024, 1024, 210944>>>(fij, rij, nbrs, nmask, bf1, bf2,
                                  (const float4*)p1, (const float4*)p2,
                                  (const float*)py, (float*)pv);
    gemmC<<<128, 512, 202752>>>((const float*)pv, (const float4*)p3, (const float4*)p4,
                                bfout, bdense, out);
}

// round 10
// speedup vs baseline: 2.3700x; 1.1553x over previous
#include <cuda_runtime.h>
#include <cstdint>

__device__ float g_y[8192*128], g_v[8192*128];
__device__ float4 g_wp0[8*16*32], g_wp1[4*16*32], g_wp2[8*16*32],
                  g_wp3[8*16*32], g_wp4[8*16*32];

__device__ __forceinline__ uint32_t pkbf(float lo, float hi) {
    uint32_t r; asm("cvt.rn.bf16x2.f32 %0, %1, %2;" : "=r"(r) : "f"(hi), "f"(lo)); return r;
}
__device__ __forceinline__ void bsplit(float x0, float x1, uint32_t& h, uint32_t& l) {
    h = pkbf(x0, x1);
    float r0 = x0 - __uint_as_float(h << 16);
    float r1 = x1 - __uint_as_float(h & 0xffff0000u);
    l = pkbf(r0, r1);
}
__device__ __forceinline__ void mma16(float* c, const uint32_t* a, uint32_t b0, uint32_t b1) {
    asm volatile("mma.sync.aligned.m16n8k16.row.col.f32.bf16.bf16.f32 "
        "{%0,%1,%2,%3},{%4,%5,%6,%7},{%8,%9},{%0,%1,%2,%3};"
        : "+f"(c[0]), "+f"(c[1]), "+f"(c[2]), "+f"(c[3])
        : "r"(a[0]), "r"(a[1]), "r"(a[2]), "r"(a[3]), "r"(b0), "r"(b1));
}
__device__ __forceinline__ float sspf(float x) {
    float e = __expf(-fabsf(x));
    return fmaxf(x, 0.f) + __logf(1.f + e) - 0.69314718055994531f;
}

// one K=16 step, 16 x NB*8 warp tile: A packed uint2 (hi,lo bf16x2), B packed float4
template <int NB>
__device__ __forceinline__ void pstep(const uint2* Ap, int lda, int m0, int kc,
                                      const float4* Bs, int lane, float (*acc)[4]) {
    int g = lane >> 2, t = lane & 3;
    const uint2* p0 = Ap + (m0 + g) * lda + kc + t;
    const uint2* p1 = p0 + 8 * lda;
    uint2 a0 = p0[0], a1 = p1[0], a2 = p0[4], a3 = p1[4];
    uint32_t ah[4] = {a0.x, a1.x, a2.x, a3.x};
    uint32_t al[4] = {a0.y, a1.y, a2.y, a3.y};
#pragma unroll
    for (int j = 0; j < NB; ++j) {
        float4 b = Bs[j * 32 + lane];
        uint32_t bh0 = __float_as_uint(b.x), bl0 = __float_as_uint(b.y);
        uint32_t bh1 = __float_as_uint(b.z), bl1 = __float_as_uint(b.w);
        mma16(acc[j], ah, bh0, bh1);
        mma16(acc[j], ah, bl0, bl1);
        mma16(acc[j], al, bh0, bh1);
    }
}

__global__ void pack5(const float* w0, const float* w1, const float* w2,
                      const float* w3, const float* w4,
                      float4* o0, float4* o1, float4* o2, float4* o3, float4* o4) {
    int b = blockIdx.x, lane = threadIdx.x, kidx = b >> 4, nb = b & 15;
    const float* W; float4* D; int K, ks;
    if (kidx < 8)       { W = w0; D = o0; K = 128; ks = kidx;      }
    else if (kidx < 12) { W = w1; D = o1; K = 50;  ks = kidx - 8;  }
    else if (kidx < 20) { W = w2; D = o2; K = 128; ks = kidx - 12; }
    else if (kidx < 28) { W = w3; D = o3; K = 128; ks = kidx - 20; }
    else                { W = w4; D = o4; K = 128; ks = kidx - 28; }
    int g = lane >> 2, t = lane & 3, n = nb * 8 + g, k0 = ks * 16 + 2 * t;
    float a = (k0 < K) ? W[n * K + k0] : 0.f, b1 = (k0 + 1 < K) ? W[n * K + k0 + 1] : 0.f;
    float c = (k0 + 8 < K) ? W[n * K + k0 + 8] : 0.f, d = (k0 + 9 < K) ? W[n * K + k0 + 9] : 0.f;
    uint32_t h0, l0, h1, l1;
    bsplit(a, b1, h0, l0); bsplit(c, d, h1, l1);
    D[(ks * 16 + nb) * 32 + lane] = make_float4(__uint_as_float(h0), __uint_as_float(l0),
                                                __uint_as_float(h1), __uint_as_float(l1));
}

// y[8192,128] = A @ W0^T
__global__ __launch_bounds__(512, 1)
void gemmB(const float* __restrict__ A, const float4* __restrict__ Bp,
           float* __restrict__ out) {
    extern __shared__ __align__(16) float sm[];
    float4* bf = (float4*)sm;
    uint2*  ap = (uint2*)(sm + 16384);
    int tid = threadIdx.x, lane = tid & 31, warp = tid >> 5;
    int wm = warp & 3, wn = warp >> 2, g = lane >> 2, t = lane & 3;
    int row0 = blockIdx.x * 64;
    for (int i = tid; i < 4096; i += 512) bf[i] = Bp[i];
    for (int i = tid; i < 4096; i += 512) {
        int r = i >> 6, cp = i & 63;
        float2 v = *(const float2*)(A + (size_t)(row0 + r) * 128 + 2 * cp);
        uint32_t h, l; bsplit(v.x, v.y, h, l);
        ap[r * 68 + cp] = make_uint2(h, l);
    }
    __syncthreads();
    float acc[4][4]{};
#pragma unroll
    for (int ks = 0; ks < 8; ++ks)
        pstep<4>(ap, 68, wm * 16, ks * 8, bf + (ks * 16 + wn * 4) * 32, lane, acc);
    int r0 = row0 + wm * 16 + g, r1 = r0 + 8;
#pragma unroll
    for (int j = 0; j < 4; ++j) {
        int c = wn * 32 + j * 8 + 2 * t;
        *(float2*)(out + (size_t)r0 * 128 + c) = make_float2(acc[j][0], acc[j][1]);
        *(float2*)(out + (size_t)r1 * 128 + c) = make_float2(acc[j][2], acc[j][3]);
    }
}

// fused tail: out = ssp(ssp(v @ W3^T + b3)) @ W4^T + b4
__global__ __launch_bounds__(512, 1)
void gemmC(const float* __restrict__ A, const float4* __restrict__ B3,
           const float4* __restrict__ B4, const float* __restrict__ b3,
           const float* __restrict__ b4, float* __restrict__ out) {
    extern __shared__ __align__(16) float sm[];
    float4* f3 = (float4*)sm;
    float4* f4 = (float4*)(sm + 16384);
    uint2*  ap = (uint2*)(sm + 32768);
    uint2*  vp = (uint2*)(sm + 41472);
    float* b3s = sm + 50176; float* b4s = sm + 50304;
    int tid = threadIdx.x, lane = tid & 31, warp = tid >> 5;
    int wm = warp & 3, wn = warp >> 2, g = lane >> 2, t = lane & 3;
    int row0 = blockIdx.x * 64;
    for (int i = tid; i < 4096; i += 512) { f3[i] = B3[i]; f4[i] = B4[i]; }
    if (tid < 128) { b3s[tid] = b3[tid]; b4s[tid] = b4[tid]; }
    for (int i = tid; i < 4096; i += 512) {
        int r = i >> 6, cp = i & 63;
        float2 v = *(const float2*)(A + (size_t)(row0 + r) * 128 + 2 * cp);
        uint32_t h, l; bsplit(v.x, v.y, h, l);
        ap[r * 68 + cp] = make_uint2(h, l);
    }
    __syncthreads();
    float acc[4][4]{};
#pragma unroll
    for (int ks = 0; ks < 8; ++ks)
        pstep<4>(ap, 68, wm * 16, ks * 8, f3 + (ks * 16 + wn * 4) * 32, lane, acc);
    int lr0 = wm * 16 + g;
#pragma unroll
    for (int j = 0; j < 4; ++j) {
        int c = wn * 32 + j * 8 + 2 * t, ci = c >> 1;
        float bb0 = b3s[c], bb1 = b3s[c + 1];
        uint32_t h, l;
        bsplit(sspf(sspf(acc[j][0] + bb0)), sspf(sspf(acc[j][1] + bb1)), h, l);
        vp[lr0 * 68 + ci] = make_uint2(h, l);
        bsplit(sspf(sspf(acc[j][2] + bb0)), sspf(sspf(acc[j][3] + bb1)), h, l);
        vp[(lr0 + 8) * 68 + ci] = make_uint2(h, l);
    }
    __syncthreads();
    float a2[4][4]{};
#pragma unroll
    for (int ks = 0; ks < 8; ++ks)
        pstep<4>(vp, 68, wm * 16, ks * 8, f4 + (ks * 16 + wn * 4) * 32, lane, a2);
    int r0 = row0 + lr0, r1 = r0 + 8;
#pragma unroll
    for (int j = 0; j < 4; ++j) {
        int c = wn * 32 + j * 8 + 2 * t;
        float bb0 = b4s[c], bb1 = b4s[c + 1];
        *(float2*)(out + (size_t)r0 * 128 + c) = make_float2(a2[j][0] + bb0, a2[j][1] + bb1);
        *(float2*)(out + (size_t)r1 * 128 + c) = make_float2(a2[j][2] + bb0, a2[j][3] + bb1);
    }
}

// fused main v5: 512 thr, 16 warps, tile 16x64, 2 atoms/iter, pipelined fij, 2 BAR/iter
__global__ __launch_bounds__(512, 1)
void main5(const float* __restrict__ fij, const float* __restrict__ rij,
           const int* __restrict__ nbrs, const float* __restrict__ nmask,
           const float* __restrict__ b1, const float* __restrict__ b2,
           const float4* __restrict__ w1g, const float4* __restrict__ w2g,
           const float* __restrict__ Y, float* __restrict__ V) {
    extern __shared__ __align__(16) float sm[];
    float4* b1f = (float4*)sm;                // 2048 f4
    float4* b2f = (float4*)(sm + 8192);       // 4096 f4
    uint2*  fjs = (uint2*)(sm + 24576);       // 128 x 34 (cols 25..31 zero)
    uint2*  w1p = (uint2*)(sm + 33280);       // 128 x 66
    float* cms = sm + 50176;                  // 2 x 128
    int*   nbs = (int*)(sm + 50432);          // 2 x 128
    float* b1s = sm + 50688; float* b2s = sm + 50816;
    float* vps = sm + 50944;                  // 8 x 128
    int tid = threadIdx.x, lane = tid & 31, warp = tid >> 5;
    int wm = warp & 7, wn = warp >> 3, g = lane >> 2, t = lane & 3;
    int ab0 = blockIdx.x * 8;

    for (int i = tid; i < 2048; i += 512) b1f[i] = w1g[i];
    for (int i = tid; i < 4096; i += 512) b2f[i] = w2g[i];
    if (tid < 128) { b1s[tid] = b1[tid]; b2s[tid] = b2[tid]; }
    for (int i = tid; i < 896; i += 512) {
        int r = i / 7, c = 25 + (i - r * 7);
        fjs[r * 34 + c] = make_uint2(0u, 0u);
    }
    {   // fjs + cms/nbs for at=0
        const float* fb = fij + (size_t)ab0 * 3200;
#pragma unroll
        for (int k = 0; k < 7; ++k) {
            int idx = tid + k * 512;
            if (idx < 3200) {
                float2 v = *(const float2*)(fb + 2 * idx);
                uint32_t h, l; bsplit(v.x, v.y, h, l);
                int r = idx / 25, cp = idx - r * 25;
                fjs[r * 34 + cp] = make_uint2(h, l);
            }
        }
        if (tid < 128) {
            cms[tid] = (rij[(size_t)ab0 * 64 + tid] <= 5.f) ? nmask[(size_t)ab0 * 64 + tid] : 0.f;
            nbs[tid] = nbrs[(size_t)ab0 * 64 + tid];
        }
    }
    __syncthreads();

    for (int at = 0; at < 4; ++at) {
        int ab = ab0 + at * 2;
        float* cmsc = cms + (at & 1) * 128;
        int*   nbsc = nbs + (at & 1) * 128;
        // GEMM1 (K=64 padded) + b1 + ssp -> packed w1p
        float a1[8][4]{};
#pragma unroll
        for (int ks = 0; ks < 4; ++ks)
            pstep<8>(fjs, 34, wm * 16, ks * 8, b1f + (ks * 16 + wn * 8) * 32, lane, a1);
        {
            int r0 = wm * 16 + g;
#pragma unroll
            for (int j = 0; j < 8; ++j) {
                int c = wn * 64 + j * 8 + 2 * t, ci = c >> 1;
                float bb0 = b1s[c], bb1 = b1s[c + 1];
                uint32_t h, l;
                bsplit(sspf(a1[j][0] + bb0), sspf(a1[j][1] + bb1), h, l);
                w1p[r0 * 66 + ci] = make_uint2(h, l);
                bsplit(sspf(a1[j][2] + bb0), sspf(a1[j][3] + bb1), h, l);
                w1p[(r0 + 8) * 66 + ci] = make_uint2(h, l);
            }
        }
        __syncthreads();
        // prefetch next iteration's fij / cms / nbs into registers
        float2 pf[7]; float ncm = 0.f; int nnb = 0;
        if (at < 3) {
            const float* fb = fij + (size_t)(ab + 2) * 3200;
#pragma unroll
            for (int k = 0; k < 7; ++k) {
                int idx = tid + k * 512;
                if (idx < 3200) pf[k] = *(const float2*)(fb + 2 * idx);
            }
            if (tid < 128) {
                float r = rij[(size_t)(ab + 2) * 64 + tid];
                ncm = (r <= 5.f) ? nmask[(size_t)(ab + 2) * 64 + tid] : 0.f;
                nnb = nbrs[(size_t)(ab + 2) * 64 + tid];
            }
        }
        // GEMM2 (K=128)
        float a2[8][4]{};
#pragma unroll
        for (int ks = 0; ks < 8; ++ks)
            pstep<8>(w1p, 66, wm * 16, ks * 8, b2f + (ks * 16 + wn * 8) * 32, lane, a2);
        // store prefetched data into the now-free tiles (consumed after end BAR)
        if (at < 3) {
#pragma unroll
            for (int k = 0; k < 7; ++k) {
                int idx = tid + k * 512;
                if (idx < 3200) {
                    uint32_t h, l; bsplit(pf[k].x, pf[k].y, h, l);
                    int r = idx / 25, cp = idx - r * 25;
                    fjs[r * 34 + cp] = make_uint2(h, l);
                }
            }
            if (tid < 128) {
                cms[((at + 1) & 1) * 128 + tid] = ncm;
                nbs[((at + 1) & 1) * 128 + tid] = nnb;
            }
        }
        // epi2: +b2, *cutoff*mask, gather y, reduce over rows
        {
            const float* yb = Y + (size_t)((ab0 >> 10) << 10) * 128;
            int r0 = wm * 16 + g, r1 = r0 + 8;
            float cm0 = cmsc[r0], cm1 = cmsc[r1];
            const float* y0 = yb + (size_t)nbsc[r0] * 128;
            const float* y1 = yb + (size_t)nbsc[r1] * 128;
            float2 p[8];
#pragma unroll
            for (int j = 0; j < 8; ++j) {
                int c = wn * 64 + j * 8 + 2 * t;
                float2 ya = *(const float2*)(y0 + c);
                float2 yc = *(const float2*)(y1 + c);
                float bb0 = b2s[c], bb1 = b2s[c + 1];
                p[j].x = (a2[j][0] + bb0) * cm0 * ya.x + (a2[j][2] + bb0) * cm1 * yc.x;
                p[j].y = (a2[j][1] + bb1) * cm0 * ya.y + (a2[j][3] + bb1) * cm1 * yc.y;
            }
#pragma unroll
            for (int j = 0; j < 8; ++j)
#pragma unroll
                for (int off = 16; off >= 4; off >>= 1) {
                    p[j].x += __shfl_down_sync(0xffffffffu, p[j].x, off);
                    p[j].y += __shfl_down_sync(0xffffffffu, p[j].y, off);
                }
            if (lane < 4)
#pragma unroll
                for (int j = 0; j < 8; ++j)
                    *(float2*)(vps + wm * 128 + wn * 64 + j * 8 + 2 * lane) = p[j];
        }
        __syncthreads();
        if (tid < 256) {
            int a = tid >> 7, c = tid & 127;
            V[(size_t)(ab + a) * 128 + c] = vps[(a * 4) * 128 + c] + vps[(a * 4 + 1) * 128 + c]
                                          + vps[(a * 4 + 2) * 128 + c] + vps[(a * 4 + 3) * 128 + c];
        }
    }
}

extern "C" void kernel_launch(void* const* d_in, const int* in_sizes, int n_in,
                              void* d_out, int out_size) {
    const float* x      = (const float*)d_in[0];
    const float* rij    = (const float*)d_in[1];
    const int*   nbrs   = (const int*)d_in[2];
    const float* nmask  = (const float*)d_in[3];
    const float* fij    = (const float*)d_in[4];
    const float* Win2f  = (const float*)d_in[5];
    const float* Wf1    = (const float*)d_in[6];
    const float* bf1    = (const float*)d_in[7];
    const float* Wf2    = (const float*)d_in[8];
    const float* bf2    = (const float*)d_in[9];
    const float* Wfout  = (const float*)d_in[10];
    const float* bfout  = (const float*)d_in[11];
    const float* Wdense = (const float*)d_in[12];
    const float* bdense = (const float*)d_in[13];
    float* out = (float*)d_out;

    cudaFuncSetAttribute(gemmB, cudaFuncAttributeMaxDynamicSharedMemorySize, 100352);
    cudaFuncSetAttribute(gemmC, cudaFuncAttributeMaxDynamicSharedMemorySize, 202752);
    cudaFuncSetAttribute(main5, cudaFuncAttributeMaxDynamicSharedMemorySize, 207872);

    void *py, *pv, *p0, *p1, *p2, *p3, *p4;
    cudaGetSymbolAddress(&py, g_y);
    cudaGetSymbolAddress(&pv, g_v);
    cudaGetSymbolAddress(&p0, g_wp0);
    cudaGetSymbolAddress(&p1, g_wp1);
    cudaGetSymbolAddress(&p2, g_wp2);
    cudaGetSymbolAddress(&p3, g_wp3);
    cudaGetSymbolAddress(&p4, g_wp4);

    pack5<<<576, 32>>>(Win2f, Wf1, Wf2, Wfout, Wdense,
                       (float4*)p0, (float4*)p1, (float4*)p2, (float4*)p3, (float4*)p4);
    gemmB<<<128, 512, 100352>>>(x, (const float4*)p0, (float*)py);
    main5<<<1024, 512, 207872>>>(fij, rij, nbrs, nmask, bf1, bf2,
                                 (const float4*)p1, (const float4*)p2,
                                 (const float*)py, (float*)pv);
    gemmC<<<128, 512, 202752>>>((const float*)pv, (const float4*)p3, (const float4*)p4,
                                bfout, bdense, out);
}

// round 11
// speedup vs baseline: 2.4116x; 1.0176x over previous
#include <cuda_runtime.h>
#include <cstdint>

__device__ float g_y[8192*128], g_v[8192*128];
__device__ float4 g_wp0[8*16*32], g_wp1[4*16*32], g_wp2[8*16*32],
                  g_wp3[8*16*32], g_wp4[8*16*32];

__device__ __forceinline__ uint32_t pkbf(float lo, float hi) {
    uint32_t r; asm("cvt.rn.bf16x2.f32 %0, %1, %2;" : "=r"(r) : "f"(hi), "f"(lo)); return r;
}
__device__ __forceinline__ void bsplit(float x0, float x1, uint32_t& h, uint32_t& l) {
    h = pkbf(x0, x1);
    float r0 = x0 - __uint_as_float(h << 16);
    float r1 = x1 - __uint_as_float(h & 0xffff0000u);
    l = pkbf(r0, r1);
}
__device__ __forceinline__ void mma16(float* c, const uint32_t* a, uint32_t b0, uint32_t b1) {
    asm volatile("mma.sync.aligned.m16n8k16.row.col.f32.bf16.bf16.f32 "
        "{%0,%1,%2,%3},{%4,%5,%6,%7},{%8,%9},{%0,%1,%2,%3};"
        : "+f"(c[0]), "+f"(c[1]), "+f"(c[2]), "+f"(c[3])
        : "r"(a[0]), "r"(a[1]), "r"(a[2]), "r"(a[3]), "r"(b0), "r"(b1));
}
__device__ __forceinline__ float sspf(float x) {
    float e = __expf(-fabsf(x));
    return fmaxf(x, 0.f) + __logf(1.f + e) - 0.69314718055994531f;
}

// one K=16 step, 16 x NB*8 warp tile. COMBO-MAJOR mma order: stage all B frags,
// then hh(j=0..NB), hl(j=0..NB), lh(j=0..NB) -> no back-to-back same-acc RAW.
template <int NB>
__device__ __forceinline__ void pstep(const uint2* Ap, int lda, int m0, int kc,
                                      const float4* Bs, int lane, float (*acc)[4]) {
    int g = lane >> 2, t = lane & 3;
    const uint2* p0 = Ap + (m0 + g) * lda + kc + t;
    const uint2* p1 = p0 + 8 * lda;
    uint2 a0 = p0[0], a1 = p1[0], a2 = p0[4], a3 = p1[4];
    uint32_t ah[4] = {a0.x, a1.x, a2.x, a3.x};
    uint32_t al[4] = {a0.y, a1.y, a2.y, a3.y};
    float4 b[NB];
#pragma unroll
    for (int j = 0; j < NB; ++j) b[j] = Bs[j * 32 + lane];
#pragma unroll
    for (int j = 0; j < NB; ++j)
        mma16(acc[j], ah, __float_as_uint(b[j].x), __float_as_uint(b[j].z));
#pragma unroll
    for (int j = 0; j < NB; ++j)
        mma16(acc[j], ah, __float_as_uint(b[j].y), __float_as_uint(b[j].w));
#pragma unroll
    for (int j = 0; j < NB; ++j)
        mma16(acc[j], al, __float_as_uint(b[j].x), __float_as_uint(b[j].z));
}

__global__ void pack5(const float* w0, const float* w1, const float* w2,
                      const float* w3, const float* w4,
                      float4* o0, float4* o1, float4* o2, float4* o3, float4* o4) {
    int b = blockIdx.x, lane = threadIdx.x, kidx = b >> 4, nb = b & 15;
    const float* W; float4* D; int K, ks;
    if (kidx < 8)       { W = w0; D = o0; K = 128; ks = kidx;      }
    else if (kidx < 12) { W = w1; D = o1; K = 50;  ks = kidx - 8;  }
    else if (kidx < 20) { W = w2; D = o2; K = 128; ks = kidx - 12; }
    else if (kidx < 28) { W = w3; D = o3; K = 128; ks = kidx - 20; }
    else                { W = w4; D = o4; K = 128; ks = kidx - 28; }
    int g = lane >> 2, t = lane & 3, n = nb * 8 + g, k0 = ks * 16 + 2 * t;
    float a = (k0 < K) ? W[n * K + k0] : 0.f, b1 = (k0 + 1 < K) ? W[n * K + k0 + 1] : 0.f;
    float c = (k0 + 8 < K) ? W[n * K + k0 + 8] : 0.f, d = (k0 + 9 < K) ? W[n * K + k0 + 9] : 0.f;
    uint32_t h0, l0, h1, l1;
    bsplit(a, b1, h0, l0); bsplit(c, d, h1, l1);
    D[(ks * 16 + nb) * 32 + lane] = make_float4(__uint_as_float(h0), __uint_as_float(l0),
                                                __uint_as_float(h1), __uint_as_float(l1));
}

// y[8192,128] = A @ W0^T
__global__ __launch_bounds__(512, 1)
void gemmB(const float* __restrict__ A, const float4* __restrict__ Bp,
           float* __restrict__ out) {
    extern __shared__ __align__(16) float sm[];
    float4* bf = (float4*)sm;
    uint2*  ap = (uint2*)(sm + 16384);
    int tid = threadIdx.x, lane = tid & 31, warp = tid >> 5;
    int wm = warp & 3, wn = warp >> 2, g = lane >> 2, t = lane & 3;
    int row0 = blockIdx.x * 64;
    for (int i = tid; i < 4096; i += 512) bf[i] = Bp[i];
    for (int i = tid; i < 4096; i += 512) {
        int r = i >> 6, cp = i & 63;
        float2 v = *(const float2*)(A + (size_t)(row0 + r) * 128 + 2 * cp);
        uint32_t h, l; bsplit(v.x, v.y, h, l);
        ap[r * 68 + cp] = make_uint2(h, l);
    }
    __syncthreads();
    float acc[4][4]{};
#pragma unroll
    for (int ks = 0; ks < 8; ++ks)
        pstep<4>(ap, 68, wm * 16, ks * 8, bf + (ks * 16 + wn * 4) * 32, lane, acc);
    int r0 = row0 + wm * 16 + g, r1 = r0 + 8;
#pragma unroll
    for (int j = 0; j < 4; ++j) {
        int c = wn * 32 + j * 8 + 2 * t;
        *(float2*)(out + (size_t)r0 * 128 + c) = make_float2(acc[j][0], acc[j][1]);
        *(float2*)(out + (size_t)r1 * 128 + c) = make_float2(acc[j][2], acc[j][3]);
    }
}

// fused tail: out = ssp(ssp(v @ W3^T + b3)) @ W4^T + b4
__global__ __launch_bounds__(512, 1)
void gemmC(const float* __restrict__ A, const float4* __restrict__ B3,
           const float4* __restrict__ B4, const float* __restrict__ b3,
           const float* __restrict__ b4, float* __restrict__ out) {
    extern __shared__ __align__(16) float sm[];
    float4* f3 = (float4*)sm;
    float4* f4 = (float4*)(sm + 16384);
    uint2*  ap = (uint2*)(sm + 32768);
    uint2*  vp = (uint2*)(sm + 41472);
    float* b3s = sm + 50176; float* b4s = sm + 50304;
    int tid = threadIdx.x, lane = tid & 31, warp = tid >> 5;
    int wm = warp & 3, wn = warp >> 2, g = lane >> 2, t = lane & 3;
    int row0 = blockIdx.x * 64;
    for (int i = tid; i < 4096; i += 512) { f3[i] = B3[i]; f4[i] = B4[i]; }
    if (tid < 128) { b3s[tid] = b3[tid]; b4s[tid] = b4[tid]; }
    for (int i = tid; i < 4096; i += 512) {
        int r = i >> 6, cp = i & 63;
        float2 v = *(const float2*)(A + (size_t)(row0 + r) * 128 + 2 * cp);
        uint32_t h, l; bsplit(v.x, v.y, h, l);
        ap[r * 68 + cp] = make_uint2(h, l);
    }
    __syncthreads();
    float acc[4][4]{};
#pragma unroll
    for (int ks = 0; ks < 8; ++ks)
        pstep<4>(ap, 68, wm * 16, ks * 8, f3 + (ks * 16 + wn * 4) * 32, lane, acc);
    int lr0 = wm * 16 + g;
#pragma unroll
    for (int j = 0; j < 4; ++j) {
        int c = wn * 32 + j * 8 + 2 * t, ci = c >> 1;
        float bb0 = b3s[c], bb1 = b3s[c + 1];
        uint32_t h, l;
        bsplit(sspf(sspf(acc[j][0] + bb0)), sspf(sspf(acc[j][1] + bb1)), h, l);
        vp[lr0 * 68 + ci] = make_uint2(h, l);
        bsplit(sspf(sspf(acc[j][2] + bb0)), sspf(sspf(acc[j][3] + bb1)), h, l);
        vp[(lr0 + 8) * 68 + ci] = make_uint2(h, l);
    }
    __syncthreads();
    float a2[4][4]{};
#pragma unroll
    for (int ks = 0; ks < 8; ++ks)
        pstep<4>(vp, 68, wm * 16, ks * 8, f4 + (ks * 16 + wn * 4) * 32, lane, a2);
    int r0 = row0 + lr0, r1 = r0 + 8;
#pragma unroll
    for (int j = 0; j < 4; ++j) {
        int c = wn * 32 + j * 8 + 2 * t;
        float bb0 = b4s[c], bb1 = b4s[c + 1];
        *(float2*)(out + (size_t)r0 * 128 + c) = make_float2(a2[j][0] + bb0, a2[j][1] + bb1);
        *(float2*)(out + (size_t)r1 * 128 + c) = make_float2(a2[j][2] + bb0, a2[j][3] + bb1);
    }
}

// fused main v6: main5 structure + combo-major pstep + split-GEMM2 prefetch
__global__ __launch_bounds__(512, 1)
void main6(const float* __restrict__ fij, const float* __restrict__ rij,
           const int* __restrict__ nbrs, const float* __restrict__ nmask,
           const float* __restrict__ b1, const float* __restrict__ b2,
           const float4* __restrict__ w1g, const float4* __restrict__ w2g,
           const float* __restrict__ Y, float* __restrict__ V) {
    extern __shared__ __align__(16) float sm[];
    float4* b1f = (float4*)sm;                // 2048 f4
    float4* b2f = (float4*)(sm + 8192);       // 4096 f4
    uint2*  fjs = (uint2*)(sm + 24576);       // 128 x 34 (cols 25..31 zero)
    uint2*  w1p = (uint2*)(sm + 33280);       // 128 x 66
    float* cms = sm + 50176;                  // 2 x 128
    int*   nbs = (int*)(sm + 50432);          // 2 x 128
    float* b1s = sm + 50688; float* b2s = sm + 50816;
    float* vps = sm + 50944;                  // 8 x 128
    int tid = threadIdx.x, lane = tid & 31, warp = tid >> 5;
    int wm = warp & 7, wn = warp >> 3, g = lane >> 2, t = lane & 3;
    int ab0 = blockIdx.x * 8;

    for (int i = tid; i < 2048; i += 512) b1f[i] = w1g[i];
    for (int i = tid; i < 4096; i += 512) b2f[i] = w2g[i];
    if (tid < 128) { b1s[tid] = b1[tid]; b2s[tid] = b2[tid]; }
    for (int i = tid; i < 896; i += 512) {
        int r = i / 7, c = 25 + (i - r * 7);
        fjs[r * 34 + c] = make_uint2(0u, 0u);
    }
    {   // fjs + cms/nbs for at=0
        const float* fb = fij + (size_t)ab0 * 3200;
#pragma unroll
        for (int k = 0; k < 7; ++k) {
            int idx = tid + k * 512;
            if (idx < 3200) {
                float2 v = *(const float2*)(fb + 2 * idx);
                uint32_t h, l; bsplit(v.x, v.y, h, l);
                int r = idx / 25, cp = idx - r * 25;
                fjs[r * 34 + cp] = make_uint2(h, l);
            }
        }
        if (tid < 128) {
            cms[tid] = (rij[(size_t)ab0 * 64 + tid] <= 5.f) ? nmask[(size_t)ab0 * 64 + tid] : 0.f;
            nbs[tid] = nbrs[(size_t)ab0 * 64 + tid];
        }
    }
    __syncthreads();

    for (int at = 0; at < 4; ++at) {
        int ab = ab0 + at * 2;
        float* cmsc = cms + (at & 1) * 128;
        int*   nbsc = nbs + (at & 1) * 128;
        // GEMM1 (K=64 padded) + b1 + ssp -> packed w1p
        float a1[8][4]{};
#pragma unroll
        for (int ks = 0; ks < 4; ++ks)
            pstep<8>(fjs, 34, wm * 16, ks * 8, b1f + (ks * 16 + wn * 8) * 32, lane, a1);
        {
            int r0 = wm * 16 + g;
#pragma unroll
            for (int j = 0; j < 8; ++j) {
                int c = wn * 64 + j * 8 + 2 * t, ci = c >> 1;
                float bb0 = b1s[c], bb1 = b1s[c + 1];
                uint32_t h, l;
                bsplit(sspf(a1[j][0] + bb0), sspf(a1[j][1] + bb1), h, l);
                w1p[r0 * 66 + ci] = make_uint2(h, l);
                bsplit(sspf(a1[j][2] + bb0), sspf(a1[j][3] + bb1), h, l);
                w1p[(r0 + 8) * 66 + ci] = make_uint2(h, l);
            }
        }
        __syncthreads();
        // prefetch next iteration's fij / cms / nbs into registers
        float2 pf[7]; float ncm = 0.f; int nnb = 0;
        if (at < 3) {
            const float* fb = fij + (size_t)(ab + 2) * 3200;
#pragma unroll
            for (int k = 0; k < 7; ++k) {
                int idx = tid + k * 512;
                if (idx < 3200) pf[k] = *(const float2*)(fb + 2 * idx);
            }
            if (tid < 128) {
                float r = rij[(size_t)(ab + 2) * 64 + tid];
                ncm = (r <= 5.f) ? nmask[(size_t)(ab + 2) * 64 + tid] : 0.f;
                nnb = nbrs[(size_t)(ab + 2) * 64 + tid];
            }
        }
        // GEMM2 (K=128) first half
        float a2[8][4]{};
#pragma unroll
        for (int ks = 0; ks < 4; ++ks)
            pstep<8>(w1p, 66, wm * 16, ks * 8, b2f + (ks * 16 + wn * 8) * 32, lane, a2);
        // drain prefetch into now-free tiles (ends pf live range mid-GEMM2)
        if (at < 3) {
#pragma unroll
            for (int k = 0; k < 7; ++k) {
                int idx = tid + k * 512;
                if (idx < 3200) {
                    uint32_t h, l; bsplit(pf[k].x, pf[k].y, h, l);
                    int r = idx / 25, cp = idx - r * 25;
                    fjs[r * 34 + cp] = make_uint2(h, l);
                }
            }
            if (tid < 128) {
                cms[((at + 1) & 1) * 128 + tid] = ncm;
                nbs[((at + 1) & 1) * 128 + tid] = nnb;
            }
        }
        // GEMM2 second half
#pragma unroll
        for (int ks = 4; ks < 8; ++ks)
            pstep<8>(w1p, 66, wm * 16, ks * 8, b2f + (ks * 16 + wn * 8) * 32, lane, a2);
        // epi2: +b2, *cutoff*mask, gather y, reduce over rows
        {
            const float* yb = Y + (size_t)((ab0 >> 10) << 10) * 128;
            int r0 = wm * 16 + g, r1 = r0 + 8;
            float cm0 = cmsc[r0], cm1 = cmsc[r1];
            const float* y0 = yb + (size_t)nbsc[r0] * 128;
            const float* y1 = yb + (size_t)nbsc[r1] * 128;
            float2 p[8];
#pragma unroll
            for (int j = 0; j < 8; ++j) {
                int c = wn * 64 + j * 8 + 2 * t;
                float2 ya = *(const float2*)(y0 + c);
                float2 yc = *(const float2*)(y1 + c);
                float bb0 = b2s[c], bb1 = b2s[c + 1];
                p[j].x = (a2[j][0] + bb0) * cm0 * ya.x + (a2[j][2] + bb0) * cm1 * yc.x;
                p[j].y = (a2[j][1] + bb1) * cm0 * ya.y + (a2[j][3] + bb1) * cm1 * yc.y;
            }
#pragma unroll
            for (int j = 0; j < 8; ++j)
#pragma unroll
                for (int off = 16; off >= 4; off >>= 1) {
                    p[j].x += __shfl_down_sync(0xffffffffu, p[j].x, off);
                    p[j].y += __shfl_down_sync(0xffffffffu, p[j].y, off);
                }
            if (lane < 4)
#pragma unroll
                for (int j = 0; j < 8; ++j)
                    *(float2*)(vps + wm * 128 + wn * 64 + j * 8 + 2 * lane) = p[j];
        }
        __syncthreads();
        if (tid < 256) {
            int a = tid >> 7, c = tid & 127;
            V[(size_t)(ab + a) * 128 + c] = vps[(a * 4) * 128 + c] + vps[(a * 4 + 1) * 128 + c]
                                          + vps[(a * 4 + 2) * 128 + c] + vps[(a * 4 + 3) * 128 + c];
        }
    }
}

extern "C" void kernel_launch(void* const* d_in, const int* in_sizes, int n_in,
                              void* d_out, int out_size) {
    const float* x      = (const float*)d_in[0];
    const float* rij    = (const float*)d_in[1];
    const int*   nbrs   = (const int*)d_in[2];
    const float* nmask  = (const float*)d_in[3];
    const float* fij    = (const float*)d_in[4];
    const float* Win2f  = (const float*)d_in[5];
    const float* Wf1    = (const float*)d_in[6];
    const float* bf1    = (const float*)d_in[7];
    const float* Wf2    = (const float*)d_in[8];
    const float* bf2    = (const float*)d_in[9];
    const float* Wfout  = (const float*)d_in[10];
    const float* bfout  = (const float*)d_in[11];
    const float* Wdense = (const float*)d_in[12];
    const float* bdense = (const float*)d_in[13];
    float* out = (float*)d_out;

    cudaFuncSetAttribute(gemmB, cudaFuncAttributeMaxDynamicSharedMemorySize, 100352);
    cudaFuncSetAttribute(gemmC, cudaFuncAttributeMaxDynamicSharedMemorySize, 202752);
    cudaFuncSetAttribute(main6, cudaFuncAttributeMaxDynamicSharedMemorySize, 207872);

    void *py, *pv, *p0, *p1, *p2, *p3, *p4;
    cudaGetSymbolAddress(&py, g_y);
    cudaGetSymbolAddress(&pv, g_v);
    cudaGetSymbolAddress(&p0, g_wp0);
    cudaGetSymbolAddress(&p1, g_wp1);
    cudaGetSymbolAddress(&p2, g_wp2);
    cudaGetSymbolAddress(&p3, g_wp3);
    cudaGetSymbolAddress(&p4, g_wp4);

    pack5<<<576, 32>>>(Win2f, Wf1, Wf2, Wfout, Wdense,
                       (float4*)p0, (float4*)p1, (float4*)p2, (float4*)p3, (float4*)p4);
    gemmB<<<128, 512, 100352>>>(x, (const float4*)p0, (float*)py);
    main6<<<1024, 512, 207872>>>(fij, rij, nbrs, nmask, bf1, bf2,
                                 (const float4*)p1, (const float4*)p2,
                                 (const float*)py, (float*)pv);
    gemmC<<<128, 512, 202752>>>((const float*)pv, (const float4*)p3, (const float4*)p4,
                                bfout, bdense, out);
}

// round 13
// speedup vs baseline: 2.8452x; 1.1798x over previous
#include <cuda_runtime.h>
#include <cstdint>

__device__ float g_y[8192*128], g_v[8192*128];
__device__ float4 g_wp0[8*16*32], g_wp1[4*16*32], g_wp2[8*16*32],
                  g_wp3[8*16*32], g_wp4[8*16*32];

__device__ __forceinline__ uint32_t pkbf(float lo, float hi) {
    uint32_t r; asm("cvt.rn.bf16x2.f32 %0, %1, %2;" : "=r"(r) : "f"(hi), "f"(lo)); return r;
}
__device__ __forceinline__ void bsplit(float x0, float x1, uint32_t& h, uint32_t& l) {
    h = pkbf(x0, x1);
    float r0 = x0 - __uint_as_float(h << 16);
    float r1 = x1 - __uint_as_float(h & 0xffff0000u);
    l = pkbf(r0, r1);
}
__device__ __forceinline__ void mma16(float* c, const uint32_t* a, uint32_t b0, uint32_t b1) {
    asm volatile("mma.sync.aligned.m16n8k16.row.col.f32.bf16.bf16.f32 "
        "{%0,%1,%2,%3},{%4,%5,%6,%7},{%8,%9},{%0,%1,%2,%3};"
        : "+f"(c[0]), "+f"(c[1]), "+f"(c[2]), "+f"(c[3])
        : "r"(a[0]), "r"(a[1]), "r"(a[2]), "r"(a[3]), "r"(b0), "r"(b1));
}
__device__ __forceinline__ float sspf(float x) {
    float e = __expf(-fabsf(x));
    return fmaxf(x, 0.f) + __logf(1.f + e) - 0.69314718055994531f;
}

template <int NB>
__device__ __forceinline__ void pstep(const uint2* Ap, int lda, int m0, int kc,
                                      const float4* Bs, int lane, float (*acc)[4]) {
    int g = lane >> 2, t = lane & 3;
    const uint2* p0 = Ap + (m0 + g) * lda + kc + t;
    const uint2* p1 = p0 + 8 * lda;
    uint2 a0 = p0[0], a1 = p1[0], a2 = p0[4], a3 = p1[4];
    uint32_t ah[4] = {a0.x, a1.x, a2.x, a3.x};
    uint32_t al[4] = {a0.y, a1.y, a2.y, a3.y};
    float4 b[NB];
#pragma unroll
    for (int j = 0; j < NB; ++j) b[j] = Bs[j * 32 + lane];
#pragma unroll
    for (int j = 0; j < NB; ++j)
        mma16(acc[j], ah, __float_as_uint(b[j].x), __float_as_uint(b[j].z));
#pragma unroll
    for (int j = 0; j < NB; ++j)
        mma16(acc[j], ah, __float_as_uint(b[j].y), __float_as_uint(b[j].w));
#pragma unroll
    for (int j = 0; j < NB; ++j)
        mma16(acc[j], al, __float_as_uint(b[j].x), __float_as_uint(b[j].z));
}

__global__ void pack5(const float* w0, const float* w1, const float* w2,
                      const float* w3, const float* w4,
                      float4* o0, float4* o1, float4* o2, float4* o3, float4* o4) {
    int b = blockIdx.x, lane = threadIdx.x, kidx = b >> 4, nb = b & 15;
    const float* W; float4* D; int K, ks;
    if (kidx < 8)       { W = w0; D = o0; K = 128; ks = kidx;      }
    else if (kidx < 12) { W = w1; D = o1; K = 50;  ks = kidx - 8;  }
    else if (kidx < 20) { W = w2; D = o2; K = 128; ks = kidx - 12; }
    else if (kidx < 28) { W = w3; D = o3; K = 128; ks = kidx - 20; }
    else                { W = w4; D = o4; K = 128; ks = kidx - 28; }
    int g = lane >> 2, t = lane & 3, n = nb * 8 + g, k0 = ks * 16 + 2 * t;
    float a = (k0 < K) ? W[n * K + k0] : 0.f, b1 = (k0 + 1 < K) ? W[n * K + k0 + 1] : 0.f;
    float c = (k0 + 8 < K) ? W[n * K + k0 + 8] : 0.f, d = (k0 + 9 < K) ? W[n * K + k0 + 9] : 0.f;
    uint32_t h0, l0, h1, l1;
    bsplit(a, b1, h0, l0); bsplit(c, d, h1, l1);
    D[(ks * 16 + nb) * 32 + lane] = make_float4(__uint_as_float(h0), __uint_as_float(l0),
                                                __uint_as_float(h1), __uint_as_float(l1));
}

__global__ void zerov(float4* p) {
    p[(size_t)blockIdx.x * 512 + threadIdx.x] = make_float4(0.f, 0.f, 0.f, 0.f);
}

__global__ __launch_bounds__(512, 1)
void gemmB(const float* __restrict__ A, const float4* __restrict__ Bp,
           float* __restrict__ out) {
    extern __shared__ __align__(16) float sm[];
    float4* bf = (float4*)sm;
    uint2*  ap = (uint2*)(sm + 16384);
    int tid = threadIdx.x, lane = tid & 31, warp = tid >> 5;
    int wm = warp & 3, wn = warp >> 2, g = lane >> 2, t = lane & 3;
    int row0 = blockIdx.x * 64;
    for (int i = tid; i < 4096; i += 512) bf[i] = Bp[i];
    for (int i = tid; i < 4096; i += 512) {
        int r = i >> 6, cp = i & 63;
        float2 v = *(const float2*)(A + (size_t)(row0 + r) * 128 + 2 * cp);
        uint32_t h, l; bsplit(v.x, v.y, h, l);
        ap[r * 68 + cp] = make_uint2(h, l);
    }
    __syncthreads();
    float acc[4][4]{};
#pragma unroll
    for (int ks = 0; ks < 8; ++ks)
        pstep<4>(ap, 68, wm * 16, ks * 8, bf + (ks * 16 + wn * 4) * 32, lane, acc);
    int r0 = row0 + wm * 16 + g, r1 = r0 + 8;
#pragma unroll
    for (int j = 0; j < 4; ++j) {
        int c = wn * 32 + j * 8 + 2 * t;
        *(float2*)(out + (size_t)r0 * 128 + c) = make_float2(acc[j][0], acc[j][1]);
        *(float2*)(out + (size_t)r1 * 128 + c) = make_float2(acc[j][2], acc[j][3]);
    }
}

__global__ __launch_bounds__(512, 1)
void gemmC(const float* __restrict__ A, const float4* __restrict__ B3,
           const float4* __restrict__ B4, const float* __restrict__ b3,
           const float* __restrict__ b4, float* __restrict__ out) {
    extern __shared__ __align__(16) float sm[];
    float4* f3 = (float4*)sm;
    float4* f4 = (float4*)(sm + 16384);
    uint2*  ap = (uint2*)(sm + 32768);
    uint2*  vp = (uint2*)(sm + 41472);
    float* b3s = sm + 50176; float* b4s = sm + 50304;
    int tid = threadIdx.x, lane = tid & 31, warp = tid >> 5;
    int wm = warp & 3, wn = warp >> 2, g = lane >> 2, t = lane & 3;
    int row0 = blockIdx.x * 64;
    for (int i = tid; i < 4096; i += 512) { f3[i] = B3[i]; f4[i] = B4[i]; }
    if (tid < 128) { b3s[tid] = b3[tid]; b4s[tid] = b4[tid]; }
    for (int i = tid; i < 4096; i += 512) {
        int r = i >> 6, cp = i & 63;
        float2 v = *(const float2*)(A + (size_t)(row0 + r) * 128 + 2 * cp);
        uint32_t h, l; bsplit(v.x, v.y, h, l);
        ap[r * 68 + cp] = make_uint2(h, l);
    }
    __syncthreads();
    float acc[4][4]{};
#pragma unroll
    for (int ks = 0; ks < 8; ++ks)
        pstep<4>(ap, 68, wm * 16, ks * 8, f3 + (ks * 16 + wn * 4) * 32, lane, acc);
    int lr0 = wm * 16 + g;
#pragma unroll
    for (int j = 0; j < 4; ++j) {
        int c = wn * 32 + j * 8 + 2 * t, ci = c >> 1;
        float bb0 = b3s[c], bb1 = b3s[c + 1];
        uint32_t h, l;
        bsplit(sspf(sspf(acc[j][0] + bb0)), sspf(sspf(acc[j][1] + bb1)), h, l);
        vp[lr0 * 68 + ci] = make_uint2(h, l);
        bsplit(sspf(sspf(acc[j][2] + bb0)), sspf(sspf(acc[j][3] + bb1)), h, l);
        vp[(lr0 + 8) * 68 + ci] = make_uint2(h, l);
    }
    __syncthreads();
    float a2[4][4]{};
#pragma unroll
    for (int ks = 0; ks < 8; ++ks)
        pstep<4>(vp, 68, wm * 16, ks * 8, f4 + (ks * 16 + wn * 4) * 32, lane, a2);
    int r0 = row0 + lr0, r1 = r0 + 8;
#pragma unroll
    for (int j = 0; j < 4; ++j) {
        int c = wn * 32 + j * 8 + 2 * t;
        float bb0 = b4s[c], bb1 = b4s[c + 1];
        *(float2*)(out + (size_t)r0 * 128 + c) = make_float2(a2[j][0] + bb0, a2[j][1] + bb1);
        *(float2*)(out + (size_t)r1 * 128 + c) = make_float2(a2[j][2] + bb0, a2[j][3] + bb1);
    }
}

// main8: per-CTA neighbor compaction (cm in {0,1}) + dense M=128 bf16x3 tiles
// smem floats: b1f 0(8192) b2f 8192(16384) fjs 24576(8704) w1p 33280(16896)
//   list 50176(3584) nbs_t 53760 ats_t 53888 b1s 54016 b2s 54144
//   wred 54272 wpre 54288 cntp 54304
__global__ __launch_bounds__(512, 1)
void main8(const float* __restrict__ fij, const float* __restrict__ rij,
           const int* __restrict__ nbrs, const float* __restrict__ nmask,
           const float* __restrict__ b1, const float* __restrict__ b2,
           const float4* __restrict__ w1g, const float4* __restrict__ w2g,
           const float* __restrict__ Y, float* __restrict__ V) {
    extern __shared__ __align__(16) float sm[];
    float4*   b1f = (float4*)sm;
    float4*   b2f = (float4*)(sm + 8192);
    uint2*    fjs = (uint2*)(sm + 24576);
    uint2*    w1p = (uint2*)(sm + 33280);
    uint32_t* list = (uint32_t*)(sm + 50176);
    int*   nbs_t = (int*)(sm + 53760);
    int*   ats_t = (int*)(sm + 53888);
    float* b1s = sm + 54016; float* b2s = sm + 54144;
    int* wred = (int*)(sm + 54272); int* wpre = (int*)(sm + 54288);
    int* cntp = (int*)(sm + 54304);
    int tid = threadIdx.x, lane = tid & 31, warp = tid >> 5;
    int wm = warp & 7, wn = warp >> 3, g = lane >> 2, t = lane & 3;
    int cta = blockIdx.x;
    int astart = cta * 55 + min(cta, 52);
    int natoms = 55 + (cta < 52 ? 1 : 0);

    for (int i = tid; i < 2048; i += 512) b1f[i] = w1g[i];
    for (int i = tid; i < 4096; i += 512) b2f[i] = w2g[i];
    if (tid < 128) { b1s[tid] = b1[tid]; b2s[tid] = b2[tid]; }
    for (int i = tid; i < 896; i += 512) {          // zero fjs K-pad pairs 25..31
        int r = i / 7, c = 25 + (i - r * 7);
        fjs[r * 34 + c] = make_uint2(0u, 0u);
    }
    // ---- ordered compaction of surviving (atom,nbh) rows ----
    int rows_total = natoms * 64;
    uint32_t grbase = (uint32_t)astart * 64;
    int myc = 0; uint32_t kept[7];
#pragma unroll
    for (int k = 0; k < 7; ++k) {
        int rr = tid * 7 + k;
        if (rr < rows_total) {
            uint32_t gr = grbase + rr;
            if (rij[gr] <= 5.f && nmask[gr] > 0.5f) kept[myc++] = gr;
        }
    }
    int x = myc;
#pragma unroll
    for (int d = 1; d < 32; d <<= 1) { int y = __shfl_up_sync(~0u, x, d); if (lane >= d) x += y; }
    if (lane == 31) wred[warp] = x;
    __syncthreads();
    if (warp == 0) {
        int w = (lane < 16) ? wred[lane] : 0, xx = w;
#pragma unroll
        for (int d = 1; d < 16; d <<= 1) { int y = __shfl_up_sync(~0u, xx, d); if (lane >= d) xx += y; }
        if (lane < 16) wpre[lane] = xx - w;
        if (lane == 15) cntp[0] = xx;
    }
    __syncthreads();
    int base = wpre[warp] + (x - myc);
    for (int k = 0; k < myc; ++k) list[base + k] = kept[k];
    int cnt = cntp[0];
    int ntile = (cnt + 127) >> 7;
    for (int i = cnt + tid; i < ntile * 128; i += 512) list[i] = 0xFFFFFFFFu;
    __syncthreads();

    for (int T = 0; T < ntile; ++T) {
        if (tid < 128) {
            uint32_t u = list[T * 128 + tid];
            if (u == 0xFFFFFFFFu) { ats_t[tid] = -1; nbs_t[tid] = 0; }
            else { ats_t[tid] = (int)(u >> 6); nbs_t[tid] = nbrs[u]; }
        }
        for (int i = tid; i < 3200; i += 512) {     // gather fij rows -> packed fjs
            int rr = i / 25, pr = i - rr * 25;
            uint32_t u = list[T * 128 + rr];
            size_t gr = (u == 0xFFFFFFFFu) ? 0 : (size_t)u;
            float2 v = *(const float2*)(fij + gr * 50 + 2 * pr);
            uint32_t h, l; bsplit(v.x, v.y, h, l);
            fjs[rr * 34 + pr] = make_uint2(h, l);
        }
        __syncthreads();
        {   // GEMM1 (K=64 padded) + b1 + ssp -> packed w1p
            float a1[8][4]{};
#pragma unroll
            for (int ks = 0; ks < 4; ++ks)
                pstep<8>(fjs, 34, wm * 16, ks * 8, b1f + (ks * 16 + wn * 8) * 32, lane, a1);
            int r0 = wm * 16 + g;
#pragma unroll
            for (int j = 0; j < 8; ++j) {
                int c = wn * 64 + j * 8 + 2 * t, ci = c >> 1;
                float bb0 = b1s[c], bb1 = b1s[c + 1];
                uint32_t h, l;
                bsplit(sspf(a1[j][0] + bb0), sspf(a1[j][1] + bb1), h, l);
                w1p[r0 * 66 + ci] = make_uint2(h, l);
                bsplit(sspf(a1[j][2] + bb0), sspf(a1[j][3] + bb1), h, l);
                w1p[(r0 + 8) * 66 + ci] = make_uint2(h, l);
            }
        }
        __syncthreads();
        float a2[8][4]{};
#pragma unroll
        for (int ks = 0; ks < 8; ++ks)
            pstep<8>(w1p, 66, wm * 16, ks * 8, b2f + (ks * 16 + wn * 8) * 32, lane, a2);
        __syncthreads();                            // all warps done reading w1p
        {   // epi2: p = (d + b2) * y[nb]  -> pw (w1p region as float[128][132])
            float* pw = (float*)w1p;
            int r0 = wm * 16 + g, r1 = r0 + 8;
            int aA = ats_t[r0], aB = ats_t[r1];
            size_t yi0 = (aA >= 0) ? ((size_t)(aA >> 10) * 1024 + nbs_t[r0]) : 0;
            size_t yi1 = (aB >= 0) ? ((size_t)(aB >> 10) * 1024 + nbs_t[r1]) : 0;
            const float* y0 = Y + yi0 * 128;
            const float* y1 = Y + yi1 * 128;
#pragma unroll
            for (int j = 0; j < 8; ++j) {
                int c = wn * 64 + j * 8 + 2 * t;
                float2 ya = *(const float2*)(y0 + c);
                float2 yc = *(const float2*)(y1 + c);
                float bb0 = b2s[c], bb1 = b2s[c + 1];
                *(float2*)(pw + r0 * 132 + c) =
                    make_float2((a2[j][0] + bb0) * ya.x, (a2[j][1] + bb1) * ya.y);
                *(float2*)(pw + r1 * 132 + c) =
                    make_float2((a2[j][2] + bb0) * yc.x, (a2[j][3] + bb1) * yc.y);
            }
        }
        __syncthreads();
        {   // phase2: segmented reduce over atom-sorted rows, atomicAdd to V
            const float* pw = (const float*)w1p;
            int f = tid & 127, q = tid >> 7;
            float s = 0.f; int cur = ats_t[q * 32];
            for (int r = q * 32; r < q * 32 + 32; ++r) {
                int a = ats_t[r];
                if (a != cur) {
                    if (cur >= 0) atomicAdd(V + (size_t)cur * 128 + f, s);
                    s = 0.f; cur = a;
                }
                s += pw[r * 132 + f];
            }
            if (cur >= 0) atomicAdd(V + (size_t)cur * 128 + f, s);
        }
        __syncthreads();
    }
}

extern "C" void kernel_launch(void* const* d_in, const int* in_sizes, int n_in,
                              void* d_out, int out_size) {
    const float* x      = (const float*)d_in[0];
    const float* rij    = (const float*)d_in[1];
    const int*   nbrs   = (const int*)d_in[2];
    const float* nmask  = (const float*)d_in[3];
    const float* fij    = (const float*)d_in[4];
    const float* Win2f  = (const float*)d_in[5];
    const float* Wf1    = (const float*)d_in[6];
    const float* bf1    = (const float*)d_in[7];
    const float* Wf2    = (const float*)d_in[8];
    const float* bf2    = (const float*)d_in[9];
    const float* Wfout  = (const float*)d_in[10];
    const float* bfout  = (const float*)d_in[11];
    const float* Wdense = (const float*)d_in[12];
    const float* bdense = (const float*)d_in[13];
    float* out = (float*)d_out;

    cudaFuncSetAttribute(gemmB, cudaFuncAttributeMaxDynamicSharedMemorySize, 100352);
    cudaFuncSetAttribute(gemmC, cudaFuncAttributeMaxDynamicSharedMemorySize, 202752);
    cudaFuncSetAttribute(main8, cudaFuncAttributeMaxDynamicSharedMemorySize, 217600);

    void *py, *pv, *p0, *p1, *p2, *p3, *p4;
    cudaGetSymbolAddress(&py, g_y);
    cudaGetSymbolAddress(&pv, g_v);
    cudaGetSymbolAddress(&p0, g_wp0);
    cudaGetSymbolAddress(&p1, g_wp1);
    cudaGetSymbolAddress(&p2, g_wp2);
    cudaGetSymbolAddress(&p3, g_wp3);
    cudaGetSymbolAddress(&p4, g_wp4);

    pack5<<<576, 32>>>(Win2f, Wf1, Wf2, Wfout, Wdense,
                       (float4*)p0, (float4*)p1, (float4*)p2, (float4*)p3, (float4*)p4);
    zerov<<<512, 512>>>((float4*)pv);
    gemmB<<<128, 512, 100352>>>(x, (const float4*)p0, (float*)py);
    main8<<<148, 512, 217600>>>(fij, rij, nbrs, nmask, bf1, bf2,
                                (const float4*)p1, (const float4*)p2,
                                (const float*)py, (float*)pv);
    gemmC<<<128, 512, 202752>>>((const float*)pv, (const float4*)p3, (const float4*)p4,
                                bfout, bdense, out);
}

// round 14
// speedup vs baseline: 3.4451x; 1.2108x over previous
#include <cuda_runtime.h>
#include <cstdint>

__device__ float g_y[8192*128], g_v[8192*128];
__device__ float4 g_wp0[8*16*32], g_wp1[4*16*32], g_wp2[8*16*32],
                  g_wp3[8*16*32], g_wp4[8*16*32];

__device__ __forceinline__ uint32_t pkbf(float lo, float hi) {
    uint32_t r; asm("cvt.rn.bf16x2.f32 %0, %1, %2;" : "=r"(r) : "f"(hi), "f"(lo)); return r;
}
__device__ __forceinline__ void bsplit(float x0, float x1, uint32_t& h, uint32_t& l) {
    h = pkbf(x0, x1);
    float r0 = x0 - __uint_as_float(h << 16);
    float r1 = x1 - __uint_as_float(h & 0xffff0000u);
    l = pkbf(r0, r1);
}
__device__ __forceinline__ void mma16(float* c, const uint32_t* a, uint32_t b0, uint32_t b1) {
    asm volatile("mma.sync.aligned.m16n8k16.row.col.f32.bf16.bf16.f32 "
        "{%0,%1,%2,%3},{%4,%5,%6,%7},{%8,%9},{%0,%1,%2,%3};"
        : "+f"(c[0]), "+f"(c[1]), "+f"(c[2]), "+f"(c[3])
        : "r"(a[0]), "r"(a[1]), "r"(a[2]), "r"(a[3]), "r"(b0), "r"(b1));
}
__device__ __forceinline__ float sspf(float x) {
    float e = __expf(-fabsf(x));
    return fmaxf(x, 0.f) + __logf(1.f + e) - 0.69314718055994531f;
}

template <int NB>
__device__ __forceinline__ void pstep(const uint2* Ap, int lda, int m0, int kc,
                                      const float4* Bs, int lane, float (*acc)[4]) {
    int g = lane >> 2, t = lane & 3;
    const uint2* p0 = Ap + (m0 + g) * lda + kc + t;
    const uint2* p1 = p0 + 8 * lda;
    uint2 a0 = p0[0], a1 = p1[0], a2 = p0[4], a3 = p1[4];
    uint32_t ah[4] = {a0.x, a1.x, a2.x, a3.x};
    uint32_t al[4] = {a0.y, a1.y, a2.y, a3.y};
    float4 b[NB];
#pragma unroll
    for (int j = 0; j < NB; ++j) b[j] = Bs[j * 32 + lane];
#pragma unroll
    for (int j = 0; j < NB; ++j)
        mma16(acc[j], ah, __float_as_uint(b[j].x), __float_as_uint(b[j].z));
#pragma unroll
    for (int j = 0; j < NB; ++j)
        mma16(acc[j], ah, __float_as_uint(b[j].y), __float_as_uint(b[j].w));
#pragma unroll
    for (int j = 0; j < NB; ++j)
        mma16(acc[j], al, __float_as_uint(b[j].x), __float_as_uint(b[j].z));
}

__global__ void pack5(const float* w0, const float* w1, const float* w2,
                      const float* w3, const float* w4,
                      float4* o0, float4* o1, float4* o2, float4* o3, float4* o4) {
    int b = blockIdx.x, lane = threadIdx.x, kidx = b >> 4, nb = b & 15;
    const float* W; float4* D; int K, ks;
    if (kidx < 8)       { W = w0; D = o0; K = 128; ks = kidx;      }
    else if (kidx < 12) { W = w1; D = o1; K = 50;  ks = kidx - 8;  }
    else if (kidx < 20) { W = w2; D = o2; K = 128; ks = kidx - 12; }
    else if (kidx < 28) { W = w3; D = o3; K = 128; ks = kidx - 20; }
    else                { W = w4; D = o4; K = 128; ks = kidx - 28; }
    int g = lane >> 2, t = lane & 3, n = nb * 8 + g, k0 = ks * 16 + 2 * t;
    float a = (k0 < K) ? W[n * K + k0] : 0.f, b1 = (k0 + 1 < K) ? W[n * K + k0 + 1] : 0.f;
    float c = (k0 + 8 < K) ? W[n * K + k0 + 8] : 0.f, d = (k0 + 9 < K) ? W[n * K + k0 + 9] : 0.f;
    uint32_t h0, l0, h1, l1;
    bsplit(a, b1, h0, l0); bsplit(c, d, h1, l1);
    D[(ks * 16 + nb) * 32 + lane] = make_float4(__uint_as_float(h0), __uint_as_float(l0),
                                                __uint_as_float(h1), __uint_as_float(l1));
}

__global__ void zerov(float4* p) {
    p[(size_t)blockIdx.x * 512 + threadIdx.x] = make_float4(0.f, 0.f, 0.f, 0.f);
}

__global__ __launch_bounds__(512, 1)
void gemmB(const float* __restrict__ A, const float4* __restrict__ Bp,
           float* __restrict__ out) {
    extern __shared__ __align__(16) float sm[];
    float4* bf = (float4*)sm;
    uint2*  ap = (uint2*)(sm + 16384);
    int tid = threadIdx.x, lane = tid & 31, warp = tid >> 5;
    int wm = warp & 3, wn = warp >> 2, g = lane >> 2, t = lane & 3;
    int row0 = blockIdx.x * 64;
    for (int i = tid; i < 4096; i += 512) bf[i] = Bp[i];
    for (int i = tid; i < 4096; i += 512) {
        int r = i >> 6, cp = i & 63;
        float2 v = *(const float2*)(A + (size_t)(row0 + r) * 128 + 2 * cp);
        uint32_t h, l; bsplit(v.x, v.y, h, l);
        ap[r * 68 + cp] = make_uint2(h, l);
    }
    __syncthreads();
    float acc[4][4]{};
#pragma unroll
    for (int ks = 0; ks < 8; ++ks)
        pstep<4>(ap, 68, wm * 16, ks * 8, bf + (ks * 16 + wn * 4) * 32, lane, acc);
    int r0 = row0 + wm * 16 + g, r1 = r0 + 8;
#pragma unroll
    for (int j = 0; j < 4; ++j) {
        int c = wn * 32 + j * 8 + 2 * t;
        *(float2*)(out + (size_t)r0 * 128 + c) = make_float2(acc[j][0], acc[j][1]);
        *(float2*)(out + (size_t)r1 * 128 + c) = make_float2(acc[j][2], acc[j][3]);
    }
}

__global__ __launch_bounds__(512, 1)
void gemmC(const float* __restrict__ A, const float4* __restrict__ B3,
           const float4* __restrict__ B4, const float* __restrict__ b3,
           const float* __restrict__ b4, float* __restrict__ out) {
    extern __shared__ __align__(16) float sm[];
    float4* f3 = (float4*)sm;
    float4* f4 = (float4*)(sm + 16384);
    uint2*  ap = (uint2*)(sm + 32768);
    uint2*  vp = (uint2*)(sm + 41472);
    float* b3s = sm + 50176; float* b4s = sm + 50304;
    int tid = threadIdx.x, lane = tid & 31, warp = tid >> 5;
    int wm = warp & 3, wn = warp >> 2, g = lane >> 2, t = lane & 3;
    int row0 = blockIdx.x * 64;
    for (int i = tid; i < 4096; i += 512) { f3[i] = B3[i]; f4[i] = B4[i]; }
    if (tid < 128) { b3s[tid] = b3[tid]; b4s[tid] = b4[tid]; }
    for (int i = tid; i < 4096; i += 512) {
        int r = i >> 6, cp = i & 63;
        float2 v = *(const float2*)(A + (size_t)(row0 + r) * 128 + 2 * cp);
        uint32_t h, l; bsplit(v.x, v.y, h, l);
        ap[r * 68 + cp] = make_uint2(h, l);
    }
    __syncthreads();
    float acc[4][4]{};
#pragma unroll
    for (int ks = 0; ks < 8; ++ks)
        pstep<4>(ap, 68, wm * 16, ks * 8, f3 + (ks * 16 + wn * 4) * 32, lane, acc);
    int lr0 = wm * 16 + g;
#pragma unroll
    for (int j = 0; j < 4; ++j) {
        int c = wn * 32 + j * 8 + 2 * t, ci = c >> 1;
        float bb0 = b3s[c], bb1 = b3s[c + 1];
        uint32_t h, l;
        bsplit(sspf(sspf(acc[j][0] + bb0)), sspf(sspf(acc[j][1] + bb1)), h, l);
        vp[lr0 * 68 + ci] = make_uint2(h, l);
        bsplit(sspf(sspf(acc[j][2] + bb0)), sspf(sspf(acc[j][3] + bb1)), h, l);
        vp[(lr0 + 8) * 68 + ci] = make_uint2(h, l);
    }
    __syncthreads();
    float a2[4][4]{};
#pragma unroll
    for (int ks = 0; ks < 8; ++ks)
        pstep<4>(vp, 68, wm * 16, ks * 8, f4 + (ks * 16 + wn * 4) * 32, lane, a2);
    int r0 = row0 + lr0, r1 = r0 + 8;
#pragma unroll
    for (int j = 0; j < 4; ++j) {
        int c = wn * 32 + j * 8 + 2 * t;
        float bb0 = b4s[c], bb1 = b4s[c + 1];
        *(float2*)(out + (size_t)r0 * 128 + c) = make_float2(a2[j][0] + bb0, a2[j][1] + bb1);
        *(float2*)(out + (size_t)r1 * 128 + c) = make_float2(a2[j][2] + bb0, a2[j][3] + bb1);
    }
}

// main9: compaction + dense tiles, software-pipelined gather, 2 syncs/tile
__global__ __launch_bounds__(512, 1)
void main9(const float* __restrict__ fij, const float* __restrict__ rij,
           const int* __restrict__ nbrs, const float* __restrict__ nmask,
           const float* __restrict__ b1, const float* __restrict__ b2,
           const float4* __restrict__ w1g, const float4* __restrict__ w2g,
           const float* __restrict__ Y, float* __restrict__ V) {
    extern __shared__ __align__(16) float sm[];
    float4*   b1f = (float4*)sm;                   // [0, 8192)
    float4*   b2f = (float4*)(sm + 8192);          // [8192, 24576)
    uint2*    fjs = (uint2*)(sm + 24576);          // 128 x 34  [24576, 33280)
    uint2*    w1p = (uint2*)(sm + 33280);          // 128 x 66  [33280, 50176)
    uint32_t* list = (uint32_t*)(sm + 50176);      // 3584
    int*   nbs_t = (int*)(sm + 53760);             // 2 x 128
    int*   ats_t = (int*)(sm + 54016);             // 2 x 128
    float* b1s = sm + 54272; float* b2s = sm + 54400;
    int* wred = (int*)(sm + 54528); int* wpre = (int*)(sm + 54544);
    int* cntp = (int*)(sm + 54560);
    int tid = threadIdx.x, lane = tid & 31, warp = tid >> 5;
    int wm = warp & 7, wn = warp >> 3, g = lane >> 2, t = lane & 3;
    int cta = blockIdx.x;
    int astart = cta * 55 + min(cta, 52);
    int natoms = 55 + (cta < 52 ? 1 : 0);

    for (int i = tid; i < 2048; i += 512) b1f[i] = w1g[i];
    for (int i = tid; i < 4096; i += 512) b2f[i] = w2g[i];
    if (tid < 128) { b1s[tid] = b1[tid]; b2s[tid] = b2[tid]; }
    for (int i = tid; i < 896; i += 512) {          // zero fjs K-pad pairs 25..31
        int r = i / 7, c = 25 + (i - r * 7);
        fjs[r * 34 + c] = make_uint2(0u, 0u);
    }
    // ---- ordered compaction of surviving (atom,nbh) rows ----
    int rows_total = natoms * 64;
    uint32_t grbase = (uint32_t)astart * 64;
    int myc = 0; uint32_t kept[7];
#pragma unroll
    for (int k = 0; k < 7; ++k) {
        int rr = tid * 7 + k;
        if (rr < rows_total) {
            uint32_t gr = grbase + rr;
            if (rij[gr] <= 5.f && nmask[gr] > 0.5f) kept[myc++] = gr;
        }
    }
    int x = myc;
#pragma unroll
    for (int d = 1; d < 32; d <<= 1) { int y = __shfl_up_sync(~0u, x, d); if (lane >= d) x += y; }
    if (lane == 31) wred[warp] = x;
    __syncthreads();
    if (warp == 0) {
        int w = (lane < 16) ? wred[lane] : 0, xx = w;
#pragma unroll
        for (int d = 1; d < 16; d <<= 1) { int y = __shfl_up_sync(~0u, xx, d); if (lane >= d) xx += y; }
        if (lane < 16) wpre[lane] = xx - w;
        if (lane == 15) cntp[0] = xx;
    }
    __syncthreads();
    int base = wpre[warp] + (x - myc);
    for (int k = 0; k < myc; ++k) list[base + k] = kept[k];
    int cnt = cntp[0];
    int ntile = (cnt + 127) >> 7;
    for (int i = cnt + tid; i < ntile * 128; i += 512) list[i] = 0xFFFFFFFFu;
    __syncthreads();

    // preload tile 0: fjs + meta(buf 0)
    for (int i = tid; i < 3200; i += 512) {
        int rr = i / 25, pr = i - rr * 25;
        uint32_t u = list[rr];
        size_t gr = (u == 0xFFFFFFFFu) ? 0 : (size_t)u;
        float2 v = *(const float2*)(fij + gr * 50 + 2 * pr);
        uint32_t h, l; bsplit(v.x, v.y, h, l);
        fjs[rr * 34 + pr] = make_uint2(h, l);
    }
    if (tid < 128) {
        uint32_t u = list[tid];
        if (u == 0xFFFFFFFFu) { ats_t[tid] = -1; nbs_t[tid] = 0; }
        else { ats_t[tid] = (int)(u >> 6); nbs_t[tid] = nbrs[u]; }
    }
    __syncthreads();

    for (int T = 0; T < ntile; ++T) {
        int buf = T & 1;
        // GEMM1 (K=64 padded) + b1 + ssp -> packed w1p (own-slab handoff)
        {
            float a1[8][4]{};
#pragma unroll
            for (int ks = 0; ks < 4; ++ks)
                pstep<8>(fjs, 34, wm * 16, ks * 8, b1f + (ks * 16 + wn * 8) * 32, lane, a1);
            int r0 = wm * 16 + g;
#pragma unroll
            for (int j = 0; j < 8; ++j) {
                int c = wn * 64 + j * 8 + 2 * t, ci = c >> 1;
                float bb0 = b1s[c], bb1 = b1s[c + 1];
                uint32_t h, l;
                bsplit(sspf(a1[j][0] + bb0), sspf(a1[j][1] + bb1), h, l);
                w1p[r0 * 66 + ci] = make_uint2(h, l);
                bsplit(sspf(a1[j][2] + bb0), sspf(a1[j][3] + bb1), h, l);
                w1p[(r0 + 8) * 66 + ci] = make_uint2(h, l);
            }
        }
        __syncwarp();
        // prefetch tile T+1 (fij rows + meta) into registers
        float2 pf[7]; int pa = -1, pn = 0;
        if (T + 1 < ntile) {
#pragma unroll
            for (int k = 0; k < 7; ++k) {
                int idx = tid + k * 512;
                if (idx < 3200) {
                    int rr = idx / 25, pr = idx - rr * 25;
                    uint32_t u = list[(T + 1) * 128 + rr];
                    size_t gr = (u == 0xFFFFFFFFu) ? 0 : (size_t)u;
                    pf[k] = *(const float2*)(fij + gr * 50 + 2 * pr);
                }
            }
            if (tid < 128) {
                uint32_t u = list[(T + 1) * 128 + tid];
                if (u != 0xFFFFFFFFu) { pa = (int)(u >> 6); pn = nbrs[u]; }
            }
        }
        // GEMM2 (K=128), reads own w1p slab
        float a2[8][4]{};
#pragma unroll
        for (int ks = 0; ks < 8; ++ks)
            pstep<8>(w1p, 66, wm * 16, ks * 8, b2f + (ks * 16 + wn * 8) * 32, lane, a2);
        // epi2: p = (d + b2) * y[nb] -> pw (own slab; per-lane same rows as read)
        {
            float* pw = (float*)w1p;
            int r0 = wm * 16 + g, r1 = r0 + 8;
            int aA = ats_t[buf * 128 + r0], aB = ats_t[buf * 128 + r1];
            size_t yi0 = (aA >= 0) ? ((size_t)(aA >> 10) * 1024 + nbs_t[buf * 128 + r0]) : 0;
            size_t yi1 = (aB >= 0) ? ((size_t)(aB >> 10) * 1024 + nbs_t[buf * 128 + r1]) : 0;
            const float* y0 = Y + yi0 * 128;
            const float* y1 = Y + yi1 * 128;
#pragma unroll
            for (int j = 0; j < 8; ++j) {
                int c = wn * 64 + j * 8 + 2 * t;
                float2 ya = *(const float2*)(y0 + c);
                float2 yc = *(const float2*)(y1 + c);
                float bb0 = b2s[c], bb1 = b2s[c + 1];
                *(float2*)(pw + r0 * 132 + c) =
                    make_float2((a2[j][0] + bb0) * ya.x, (a2[j][1] + bb1) * ya.y);
                *(float2*)(pw + r1 * 132 + c) =
                    make_float2((a2[j][2] + bb0) * yc.x, (a2[j][3] + bb1) * yc.y);
            }
        }
        __syncthreads();    // #1: pw visible to all; fjs free (GEMM1 reads done)
        // drain prefetch: fjs[T+1] + meta[buf^1]
        if (T + 1 < ntile) {
#pragma unroll
            for (int k = 0; k < 7; ++k) {
                int idx = tid + k * 512;
                if (idx < 3200) {
                    int rr = idx / 25, pr = idx - rr * 25;
                    uint32_t h, l; bsplit(pf[k].x, pf[k].y, h, l);
                    fjs[rr * 34 + pr] = make_uint2(h, l);
                }
            }
            if (tid < 128) { ats_t[(buf ^ 1) * 128 + tid] = pa; nbs_t[(buf ^ 1) * 128 + tid] = pn; }
        }
        // segmented reduce over atom-sorted rows -> atomicAdd V
        {
            const float* pw = (const float*)w1p;
            int f = tid & 127, q = tid >> 7;
            float s = 0.f; int cur = ats_t[buf * 128 + q * 32];
            for (int r = q * 32; r < q * 32 + 32; ++r) {
                int a = ats_t[buf * 128 + r];
                if (a != cur) {
                    if (cur >= 0) atomicAdd(V + (size_t)cur * 128 + f, s);
                    s = 0.f; cur = a;
                }
                s += pw[r * 132 + f];
            }
            if (cur >= 0) atomicAdd(V + (size_t)cur * 128 + f, s);
        }
        __syncthreads();    // #2: pw free for next w1p write; fjs[T+1] ready
    }
}

extern "C" void kernel_launch(void* const* d_in, const int* in_sizes, int n_in,
                              void* d_out, int out_size) {
    const float* x      = (const float*)d_in[0];
    const float* rij    = (const float*)d_in[1];
    const int*   nbrs   = (const int*)d_in[2];
    const float* nmask  = (const float*)d_in[3];
    const float* fij    = (const float*)d_in[4];
    const float* Win2f  = (const float*)d_in[5];
    const float* Wf1    = (const float*)d_in[6];
    const float* bf1    = (const float*)d_in[7];
    const float* Wf2    = (const float*)d_in[8];
    const float* bf2    = (const float*)d_in[9];
    const float* Wfout  = (const float*)d_in[10];
    const float* bfout  = (const float*)d_in[11];
    const float* Wdense = (const float*)d_in[12];
    const float* bdense = (const float*)d_in[13];
    float* out = (float*)d_out;

    cudaFuncSetAttribute(gemmB, cudaFuncAttributeMaxDynamicSharedMemorySize, 100352);
    cudaFuncSetAttribute(gemmC, cudaFuncAttributeMaxDynamicSharedMemorySize, 202752);
    cudaFuncSetAttribute(main9, cudaFuncAttributeMaxDynamicSharedMemorySize, 218304);

    void *py, *pv, *p0, *p1, *p2, *p3, *p4;
    cudaGetSymbolAddress(&py, g_y);
    cudaGetSymbolAddress(&pv, g_v);
    cudaGetSymbolAddress(&p0, g_wp0);
    cudaGetSymbolAddress(&p1, g_wp1);
    cudaGetSymbolAddress(&p2, g_wp2);
    cudaGetSymbolAddress(&p3, g_wp3);
    cudaGetSymbolAddress(&p4, g_wp4);

    pack5<<<576, 32>>>(Win2f, Wf1, Wf2, Wfout, Wdense,
                       (float4*)p0, (float4*)p1, (float4*)p2, (float4*)p3, (float4*)p4);
    zerov<<<512, 512>>>((float4*)pv);
    gemmB<<<128, 512, 100352>>>(x, (const float4*)p0, (float*)py);
    main9<<<148, 512, 218304>>>(fij, rij, nbrs, nmask, bf1, bf2,
                                (const float4*)p1, (const float4*)p2,
                                (const float*)py, (float*)pv);
    gemmC<<<128, 512, 202752>>>((const float*)pv, (const float4*)p3, (const float4*)p4,
                                bfout, bdense, out);
}